// round 3
// baseline (speedup 1.0000x reference)
#include <cuda_runtime.h>
#include <cfloat>

// Problem constants (fixed shapes for this problem instance)
#define N_NODES  50000
#define N_EDGES  1600000
#define IN_DIM   128
#define OUT_DIM  32
#define N_HEADS  4
#define TOT_OUT  (N_HEADS * OUT_DIM)   // 128

// ---------------- scratch (device globals; no allocations allowed) ----------
__device__ float g_Wh[(size_t)N_NODES * TOT_OUT];     // 25.6 MB
__device__ float g_ssrc[(size_t)N_NODES * N_HEADS];   // 800 KB
__device__ float g_sdst[(size_t)N_NODES * N_HEADS];   // 800 KB
__device__ float g_max[(size_t)N_NODES * N_HEADS];    // 800 KB
__device__ float g_sum[(size_t)N_NODES * N_HEADS];    // 800 KB
__device__ float g_e[(size_t)N_EDGES * N_HEADS];      // 25.6 MB

// ---------------- helpers ----------------------------------------------------
__device__ __forceinline__ void atomicMaxF(float* addr, float val) {
    int iv = __float_as_int(val);
    if (iv >= 0) {
        atomicMax((int*)addr, iv);
    } else {
        atomicMin((unsigned int*)addr, __float_as_uint(val));
    }
}

__device__ __forceinline__ void redAdd4(float* p, float4 v) {
    asm volatile("red.global.add.v4.f32 [%0], {%1,%2,%3,%4};"
                 :: "l"(p), "f"(v.x), "f"(v.y), "f"(v.z), "f"(v.w) : "memory");
}

__device__ __forceinline__ float lrelu(float v) {
    return v > 0.0f ? v : 0.2f * v;
}

// ---------------- kernel 1: Wh = x @ W  (per-head projection) ---------------
// Wh[n, h*32+o] = sum_i x[n,i] * weight[h,i,o]
#define GEMM_NB 64
#define GEMM_CK 32
#define GEMM_TPB 256

__global__ void gemm_kernel(const float* __restrict__ x,
                            const float* __restrict__ wt) {
    __shared__ float xs[GEMM_NB][GEMM_CK];
    __shared__ float ws[GEMM_CK][TOT_OUT];

    const int n0   = blockIdx.x * GEMM_NB;
    const int tid  = threadIdx.x;
    const int warp = tid >> 5;
    const int lane = tid & 31;

    float acc[8][4];
#pragma unroll
    for (int j = 0; j < 8; j++) { acc[j][0]=0.f; acc[j][1]=0.f; acc[j][2]=0.f; acc[j][3]=0.f; }

    for (int k0 = 0; k0 < IN_DIM; k0 += GEMM_CK) {
        for (int idx = tid; idx < GEMM_CK * TOT_OUT; idx += GEMM_TPB) {
            int ki = idx >> 7;         // /128
            int c  = idx & 127;
            ws[ki][c] = wt[(c >> 5) * (IN_DIM * OUT_DIM) + (k0 + ki) * OUT_DIM + (c & 31)];
        }
        for (int idx = tid; idx < GEMM_NB * GEMM_CK; idx += GEMM_TPB) {
            int nl = idx / GEMM_CK;
            int ki = idx % GEMM_CK;
            int n  = n0 + nl;
            xs[nl][ki] = (n < N_NODES) ? x[(size_t)n * IN_DIM + k0 + ki] : 0.f;
        }
        __syncthreads();

#pragma unroll
        for (int ki = 0; ki < GEMM_CK; ki++) {
            float4 wv = *(const float4*)&ws[ki][lane * 4];
#pragma unroll
            for (int j = 0; j < 8; j++) {
                float xv = xs[warp * 8 + j][ki];
                acc[j][0] += xv * wv.x;
                acc[j][1] += xv * wv.y;
                acc[j][2] += xv * wv.z;
                acc[j][3] += xv * wv.w;
            }
        }
        __syncthreads();
    }

#pragma unroll
    for (int j = 0; j < 8; j++) {
        int n = n0 + warp * 8 + j;
        if (n < N_NODES) {
            float4 v = make_float4(acc[j][0], acc[j][1], acc[j][2], acc[j][3]);
            *(float4*)&g_Wh[(size_t)n * TOT_OUT + lane * 4] = v;
        }
    }
}

// ---------------- kernel 2: per-node attention scalars -----------------------
__global__ void score_kernel(const float* __restrict__ at) {
    const int n   = blockIdx.x;
    const int tid = threadIdx.x;    // 128 threads = 4 heads x 32 outs
    const int h   = tid >> 5;
    const int o   = tid & 31;

    float v  = g_Wh[(size_t)n * TOT_OUT + tid];
    float ps = v * at[h * (2 * OUT_DIM) + o];
    float pd = v * at[h * (2 * OUT_DIM) + OUT_DIM + o];

#pragma unroll
    for (int off = 16; off > 0; off >>= 1) {
        ps += __shfl_xor_sync(0xffffffffu, ps, off);
        pd += __shfl_xor_sync(0xffffffffu, pd, off);
    }
    if (o == 0) {
        g_ssrc[n * N_HEADS + h] = ps;
        g_sdst[n * N_HEADS + h] = pd;
    }
}

// ---------------- kernel 3: init (zero out_h, init max/sum) ------------------
__global__ void init_kernel(float* __restrict__ out_h) {
    long long i = (long long)blockIdx.x * blockDim.x + threadIdx.x;
    if (i < (long long)N_NODES * TOT_OUT) out_h[i] = 0.0f;
    if (i < (long long)N_NODES * N_HEADS) {
        g_max[i] = -FLT_MAX;
        g_sum[i] = 0.0f;
    }
}

// ---------------- kernel 4: edge pass 1 (score + segment max) ----------------
// edge_index is int32 pairs (JAX x64 disabled downgrades int64 -> int32).
__global__ void pass1_kernel(const int* __restrict__ ei) {
    int e = blockIdx.x * blockDim.x + threadIdx.x;
    if (e >= N_EDGES) return;
    int2 p = ((const int2*)ei)[e];
    int src = p.x, dst = p.y;
    if ((unsigned)src >= N_NODES || (unsigned)dst >= N_NODES) return;

    float4 ss = *(const float4*)&g_ssrc[src * N_HEADS];
    float4 sd = *(const float4*)&g_sdst[dst * N_HEADS];
    float4 v;
    v.x = lrelu(ss.x + sd.x);
    v.y = lrelu(ss.y + sd.y);
    v.z = lrelu(ss.z + sd.z);
    v.w = lrelu(ss.w + sd.w);
    *(float4*)&g_e[(size_t)e * N_HEADS] = v;

    float* mp = &g_max[dst * N_HEADS];
    atomicMaxF(mp + 0, v.x);
    atomicMaxF(mp + 1, v.y);
    atomicMaxF(mp + 2, v.z);
    atomicMaxF(mp + 3, v.w);
}

// ---------------- kernel 5: edge pass 2 (exp + segment sum) ------------------
__global__ void pass2_kernel(const int* __restrict__ ei) {
    int e = blockIdx.x * blockDim.x + threadIdx.x;
    if (e >= N_EDGES) return;
    int dst = ((const int2*)ei)[e].y;
    if ((unsigned)dst >= N_NODES) return;

    float4 m4 = *(const float4*)&g_max[dst * N_HEADS];
    float4 ev = *(const float4*)&g_e[(size_t)e * N_HEADS];
    float4 ex;
    ex.x = __expf(ev.x - m4.x);
    ex.y = __expf(ev.y - m4.y);
    ex.z = __expf(ev.z - m4.z);
    ex.w = __expf(ev.w - m4.w);
    *(float4*)&g_e[(size_t)e * N_HEADS] = ex;

    redAdd4(&g_sum[dst * N_HEADS], ex);
}

// ---------------- kernel 6: edge pass 3 (alpha + scatter) --------------------
// One warp per edge: 32 lanes x float4 cover the 128-wide Wh row.
__global__ void pass3_kernel(const int* __restrict__ ei,
                             float* __restrict__ out_h,
                             float* __restrict__ out_alpha) {
    const int warp = threadIdx.x >> 5;
    const int lane = threadIdx.x & 31;
    int e = blockIdx.x * 8 + warp;
    if (e >= N_EDGES) return;

    int2 p = ((const int2*)ei)[e];
    int src = p.x, dst = p.y;
    if ((unsigned)src >= N_NODES || (unsigned)dst >= N_NODES) return;

    float4 ex4 = *(const float4*)&g_e[(size_t)e * N_HEADS];
    float4 s4  = *(const float4*)&g_sum[dst * N_HEADS];
    float ax = ex4.x / (s4.x + 1e-9f);
    float ay = ex4.y / (s4.y + 1e-9f);
    float az = ex4.z / (s4.z + 1e-9f);
    float aw = ex4.w / (s4.w + 1e-9f);

    if (lane == 0) {
        *(float4*)&out_alpha[(size_t)e * N_HEADS] = make_float4(ax, ay, az, aw);
    }

    float4 wv = *(const float4*)&g_Wh[(size_t)src * TOT_OUT + lane * 4];
    int h = lane >> 3;
    float a = (h == 0) ? ax : (h == 1) ? ay : (h == 2) ? az : aw;
    float4 c4 = make_float4(a * wv.x, a * wv.y, a * wv.z, a * wv.w);

    redAdd4(&out_h[(size_t)dst * TOT_OUT + lane * 4], c4);
}

// ---------------- launch -----------------------------------------------------
extern "C" void kernel_launch(void* const* d_in, const int* in_sizes, int n_in,
                              void* d_out, int out_size) {
    const float* x  = (const float*)d_in[0];
    const int*   ei = (const int*)d_in[1];
    const float* wt = (const float*)d_in[2];
    const float* at = (const float*)d_in[3];

    float* out_h     = (float*)d_out;                                   // [50000*128]
    float* out_alpha = (float*)d_out + (size_t)N_NODES * TOT_OUT;       // [1.6M*4]

    // 1. projection GEMM
    gemm_kernel<<<(N_NODES + GEMM_NB - 1) / GEMM_NB, GEMM_TPB>>>(x, wt);

    // 2. per-node score scalars
    score_kernel<<<N_NODES, TOT_OUT>>>(at);

    // 3. init output / max / sum
    {
        long long tot = (long long)N_NODES * TOT_OUT;
        int blocks = (int)((tot + 255) / 256);
        init_kernel<<<blocks, 256>>>(out_h);
    }

    // 4. edge score + segment max
    pass1_kernel<<<(N_EDGES + 255) / 256, 256>>>(ei);

    // 5. exp + segment sum
    pass2_kernel<<<(N_EDGES + 255) / 256, 256>>>(ei);

    // 6. alpha + weighted scatter-add (one warp per edge)
    pass3_kernel<<<(N_EDGES + 7) / 8, 256>>>(ei, out_h, out_alpha);

    (void)in_sizes; (void)n_in; (void)out_size;
}

// round 4
// speedup vs baseline: 1.2033x; 1.2033x over previous
#include <cuda_runtime.h>
#include <cfloat>

// Problem constants (fixed shapes for this problem instance)
#define N_NODES  50000
#define N_EDGES  1600000
#define IN_DIM   128
#define OUT_DIM  32
#define N_HEADS  4
#define TOT_OUT  (N_HEADS * OUT_DIM)   // 128

// ---------------- scratch (device globals; no allocations allowed) ----------
__device__ float g_Wh[(size_t)N_NODES * TOT_OUT];     // 25.6 MB
__device__ float g_ssrc[(size_t)N_NODES * N_HEADS];   // 800 KB
__device__ float g_sdst[(size_t)N_NODES * N_HEADS];   // 800 KB
__device__ float g_exp[(size_t)N_EDGES * N_HEADS];    // 25.6 MB  exp(e) per edge
__device__ int   g_cnt[N_NODES];                      // in-degree histogram
__device__ int   g_off[N_NODES + 1];                  // CSR offsets
__device__ int   g_cur[N_NODES];                      // scatter cursors
__device__ int2  g_csr[(size_t)N_EDGES];              // (eid, src) per CSR slot

// ---------------- helpers ----------------------------------------------------
__device__ __forceinline__ float lrelu(float v) {
    return v > 0.0f ? v : 0.2f * v;
}

// ---------------- kernel 1: Wh = x @ W  (per-head projection) ---------------
#define GEMM_NB 64
#define GEMM_CK 32
#define GEMM_TPB 256

__global__ void gemm_kernel(const float* __restrict__ x,
                            const float* __restrict__ wt) {
    __shared__ float xs[GEMM_NB][GEMM_CK];
    __shared__ float ws[GEMM_CK][TOT_OUT];

    const int n0   = blockIdx.x * GEMM_NB;
    const int tid  = threadIdx.x;
    const int warp = tid >> 5;
    const int lane = tid & 31;

    float acc[8][4];
#pragma unroll
    for (int j = 0; j < 8; j++) { acc[j][0]=0.f; acc[j][1]=0.f; acc[j][2]=0.f; acc[j][3]=0.f; }

    for (int k0 = 0; k0 < IN_DIM; k0 += GEMM_CK) {
        for (int idx = tid; idx < GEMM_CK * TOT_OUT; idx += GEMM_TPB) {
            int ki = idx >> 7;
            int c  = idx & 127;
            ws[ki][c] = wt[(c >> 5) * (IN_DIM * OUT_DIM) + (k0 + ki) * OUT_DIM + (c & 31)];
        }
        for (int idx = tid; idx < GEMM_NB * GEMM_CK; idx += GEMM_TPB) {
            int nl = idx / GEMM_CK;
            int ki = idx % GEMM_CK;
            int n  = n0 + nl;
            xs[nl][ki] = (n < N_NODES) ? x[(size_t)n * IN_DIM + k0 + ki] : 0.f;
        }
        __syncthreads();

#pragma unroll
        for (int ki = 0; ki < GEMM_CK; ki++) {
            float4 wv = *(const float4*)&ws[ki][lane * 4];
#pragma unroll
            for (int j = 0; j < 8; j++) {
                float xv = xs[warp * 8 + j][ki];
                acc[j][0] += xv * wv.x;
                acc[j][1] += xv * wv.y;
                acc[j][2] += xv * wv.z;
                acc[j][3] += xv * wv.w;
            }
        }
        __syncthreads();
    }

#pragma unroll
    for (int j = 0; j < 8; j++) {
        int n = n0 + warp * 8 + j;
        if (n < N_NODES) {
            float4 v = make_float4(acc[j][0], acc[j][1], acc[j][2], acc[j][3]);
            *(float4*)&g_Wh[(size_t)n * TOT_OUT + lane * 4] = v;
        }
    }
}

// ---------------- kernel 2: per-node attention scalars -----------------------
__global__ void score_kernel(const float* __restrict__ at) {
    const int n   = blockIdx.x;
    const int tid = threadIdx.x;    // 128 threads = 4 heads x 32 outs
    const int h   = tid >> 5;
    const int o   = tid & 31;

    float v  = g_Wh[(size_t)n * TOT_OUT + tid];
    float ps = v * at[h * (2 * OUT_DIM) + o];
    float pd = v * at[h * (2 * OUT_DIM) + OUT_DIM + o];

#pragma unroll
    for (int off = 16; off > 0; off >>= 1) {
        ps += __shfl_xor_sync(0xffffffffu, ps, off);
        pd += __shfl_xor_sync(0xffffffffu, pd, off);
    }
    if (o == 0) {
        g_ssrc[n * N_HEADS + h] = ps;
        g_sdst[n * N_HEADS + h] = pd;
    }
}

// ---------------- kernel 3: init (zero histogram) ----------------------------
__global__ void init_kernel() {
    int i = blockIdx.x * blockDim.x + threadIdx.x;
    if (i < N_NODES) g_cnt[i] = 0;
}

// ---------------- kernel 4: edge pass A (exp score + degree histogram) -------
// edge_index is int32 pairs (JAX x64 disabled downgrades int64 -> int32).
__global__ void passA_kernel(const int* __restrict__ ei) {
    int e = blockIdx.x * blockDim.x + threadIdx.x;
    if (e >= N_EDGES) return;
    int2 p = ((const int2*)ei)[e];
    int src = p.x, dst = p.y;
    if ((unsigned)src >= N_NODES || (unsigned)dst >= N_NODES) return;

    float4 ss = *(const float4*)&g_ssrc[src * N_HEADS];
    float4 sd = *(const float4*)&g_sdst[dst * N_HEADS];
    float4 v;
    v.x = __expf(lrelu(ss.x + sd.x));
    v.y = __expf(lrelu(ss.y + sd.y));
    v.z = __expf(lrelu(ss.z + sd.z));
    v.w = __expf(lrelu(ss.w + sd.w));
    *(float4*)&g_exp[(size_t)e * N_HEADS] = v;

    atomicAdd(&g_cnt[dst], 1);
}

// ---------------- kernel 5: exclusive scan of degrees -> offsets + cursors ---
#define SCAN_T 1024
__global__ void scan_kernel() {
    __shared__ int part[SCAN_T];
    const int t = threadIdx.x;
    const int chunk = (N_NODES + SCAN_T - 1) / SCAN_T;   // 49
    const int lo = t * chunk;
    const int hi = min(lo + chunk, N_NODES);

    int s = 0;
    for (int i = lo; i < hi; i++) s += g_cnt[i];
    part[t] = s;
    __syncthreads();

    // in-place Hillis-Steele inclusive scan
    for (int off = 1; off < SCAN_T; off <<= 1) {
        int v = (t >= off) ? part[t - off] : 0;
        __syncthreads();
        part[t] += v;
        __syncthreads();
    }

    int run = part[t] - s;   // exclusive prefix of this thread's chunk
    for (int i = lo; i < hi; i++) {
        g_off[i] = run;
        g_cur[i] = run;
        run += g_cnt[i];
    }
    if (t == 0) g_off[N_NODES] = N_EDGES;
}

// ---------------- kernel 6: edge pass B (CSR scatter) ------------------------
__global__ void passB_kernel(const int* __restrict__ ei) {
    int e = blockIdx.x * blockDim.x + threadIdx.x;
    if (e >= N_EDGES) return;
    int2 p = ((const int2*)ei)[e];
    int src = p.x, dst = p.y;
    if ((unsigned)src >= N_NODES || (unsigned)dst >= N_NODES) return;

    int pos = atomicAdd(&g_cur[dst], 1);
    g_csr[pos] = make_int2(e, src);
}

// ---------------- kernel 7: gather (softmax-normalize + weighted sum) --------
// One warp per dst node. 32 lanes x float4 cover the 128-wide output row.
__global__ void gather_kernel(float* __restrict__ out_h,
                              float* __restrict__ out_alpha) {
    const int warp = threadIdx.x >> 5;
    const int lane = threadIdx.x & 31;
    const int d = blockIdx.x * 8 + warp;
    if (d >= N_NODES) return;

    const int beg = g_off[d];
    const int end = g_off[d + 1];

    // 1) sum of exp over incoming edges (lanes strided over edges)
    float4 sum = make_float4(0.f, 0.f, 0.f, 0.f);
    for (int i = beg + lane; i < end; i += 32) {
        int eid = g_csr[i].x;
        float4 ex = *(const float4*)&g_exp[(size_t)eid * N_HEADS];
        sum.x += ex.x; sum.y += ex.y; sum.z += ex.z; sum.w += ex.w;
    }
#pragma unroll
    for (int off = 16; off > 0; off >>= 1) {
        sum.x += __shfl_xor_sync(0xffffffffu, sum.x, off);
        sum.y += __shfl_xor_sync(0xffffffffu, sum.y, off);
        sum.z += __shfl_xor_sync(0xffffffffu, sum.z, off);
        sum.w += __shfl_xor_sync(0xffffffffu, sum.w, off);
    }
    float4 rcp;
    rcp.x = 1.0f / (sum.x + 1e-9f);
    rcp.y = 1.0f / (sum.y + 1e-9f);
    rcp.z = 1.0f / (sum.z + 1e-9f);
    rcp.w = 1.0f / (sum.w + 1e-9f);

    // 2) per-edge: alpha + accumulate alpha * Wh[src]
    float4 acc = make_float4(0.f, 0.f, 0.f, 0.f);
    const int hsel = lane >> 3;   // which head this lane's 4 outputs belong to
    for (int i = beg; i < end; i++) {
        int2 ce = g_csr[i];                         // broadcast load (same addr all lanes)
        float4 ex = *(const float4*)&g_exp[(size_t)ce.x * N_HEADS];
        float4 a4;
        a4.x = ex.x * rcp.x;
        a4.y = ex.y * rcp.y;
        a4.z = ex.z * rcp.z;
        a4.w = ex.w * rcp.w;
        if (lane == 0) {
            *(float4*)&out_alpha[(size_t)ce.x * N_HEADS] = a4;
        }
        float4 wv = *(const float4*)&g_Wh[(size_t)ce.y * TOT_OUT + lane * 4];
        float a = (hsel == 0) ? a4.x : (hsel == 1) ? a4.y : (hsel == 2) ? a4.z : a4.w;
        acc.x += a * wv.x;
        acc.y += a * wv.y;
        acc.z += a * wv.z;
        acc.w += a * wv.w;
    }

    *(float4*)&out_h[(size_t)d * TOT_OUT + lane * 4] = acc;
}

// ---------------- launch -----------------------------------------------------
extern "C" void kernel_launch(void* const* d_in, const int* in_sizes, int n_in,
                              void* d_out, int out_size) {
    const float* x  = (const float*)d_in[0];
    const int*   ei = (const int*)d_in[1];
    const float* wt = (const float*)d_in[2];
    const float* at = (const float*)d_in[3];

    float* out_h     = (float*)d_out;                                   // [50000*128]
    float* out_alpha = (float*)d_out + (size_t)N_NODES * TOT_OUT;       // [1.6M*4]

    // 1. projection GEMM
    gemm_kernel<<<(N_NODES + GEMM_NB - 1) / GEMM_NB, GEMM_TPB>>>(x, wt);

    // 2. per-node score scalars
    score_kernel<<<N_NODES, TOT_OUT>>>(at);

    // 3. zero degree histogram
    init_kernel<<<(N_NODES + 255) / 256, 256>>>();

    // 4. edge scores (exp, no max needed) + in-degree histogram
    passA_kernel<<<(N_EDGES + 255) / 256, 256>>>(ei);

    // 5. scan degrees -> CSR offsets
    scan_kernel<<<1, SCAN_T>>>();

    // 6. scatter edges into CSR buckets
    passB_kernel<<<(N_EDGES + 255) / 256, 256>>>(ei);

    // 7. softmax-normalize + gather-accumulate per dst node
    gather_kernel<<<(N_NODES + 7) / 8, 256>>>(out_h, out_alpha);

    (void)in_sizes; (void)n_in; (void)out_size;
}

// round 5
// speedup vs baseline: 1.4533x; 1.2077x over previous
#include <cuda_runtime.h>
#include <cfloat>

// Problem constants (fixed shapes for this problem instance)
#define N_NODES  50000
#define N_EDGES  1600000
#define IN_DIM   128
#define OUT_DIM  32
#define N_HEADS  4
#define TOT_OUT  (N_HEADS * OUT_DIM)   // 128

// ---------------- scratch (device globals; no allocations allowed) ----------
__device__ float g_Wh[(size_t)N_NODES * TOT_OUT];     // 25.6 MB
__device__ float g_ssrc[(size_t)N_NODES * N_HEADS];   // 800 KB
__device__ float g_sdst[(size_t)N_NODES * N_HEADS];   // 800 KB
__device__ float g_exp[(size_t)N_EDGES * N_HEADS];    // 25.6 MB  exp(e) in CSR order
__device__ int   g_cnt[N_NODES];                      // in-degree histogram
__device__ int   g_off[N_NODES + 1];                  // CSR offsets
__device__ int   g_cur[N_NODES];                      // scatter cursors
__device__ int2  g_csr[(size_t)N_EDGES];              // (eid, src) per CSR slot

// ---------------- helpers ----------------------------------------------------
__device__ __forceinline__ float lrelu(float v) {
    return v > 0.0f ? v : 0.2f * v;
}

// ---------------- kernel 1: Wh = x @ W, fused attention-score epilogue ------
#define GEMM_NB 64
#define GEMM_CK 32
#define GEMM_TPB 256

__global__ void gemm_kernel(const float* __restrict__ x,
                            const float* __restrict__ wt,
                            const float* __restrict__ at) {
    __shared__ float xs[GEMM_NB][GEMM_CK];
    __shared__ float ws[GEMM_CK][TOT_OUT];

    const int n0   = blockIdx.x * GEMM_NB;
    const int tid  = threadIdx.x;
    const int warp = tid >> 5;
    const int lane = tid & 31;
    const int h    = lane >> 3;        // head owned by this lane's 4 columns
    const int og   = (lane & 7) * 4;   // first out-col within head

    float acc[8][4];
#pragma unroll
    for (int j = 0; j < 8; j++) { acc[j][0]=0.f; acc[j][1]=0.f; acc[j][2]=0.f; acc[j][3]=0.f; }

    for (int k0 = 0; k0 < IN_DIM; k0 += GEMM_CK) {
        for (int idx = tid; idx < GEMM_CK * TOT_OUT; idx += GEMM_TPB) {
            int ki = idx >> 7;
            int c  = idx & 127;
            ws[ki][c] = wt[(c >> 5) * (IN_DIM * OUT_DIM) + (k0 + ki) * OUT_DIM + (c & 31)];
        }
        for (int idx = tid; idx < GEMM_NB * GEMM_CK; idx += GEMM_TPB) {
            int nl = idx / GEMM_CK;
            int ki = idx % GEMM_CK;
            int n  = n0 + nl;
            xs[nl][ki] = (n < N_NODES) ? x[(size_t)n * IN_DIM + k0 + ki] : 0.f;
        }
        __syncthreads();

#pragma unroll
        for (int ki = 0; ki < GEMM_CK; ki++) {
            float4 wv = *(const float4*)&ws[ki][lane * 4];
#pragma unroll
            for (int j = 0; j < 8; j++) {
                float xv = xs[warp * 8 + j][ki];
                acc[j][0] += xv * wv.x;
                acc[j][1] += xv * wv.y;
                acc[j][2] += xv * wv.z;
                acc[j][3] += xv * wv.w;
            }
        }
        __syncthreads();
    }

    // attention vectors for this lane's 4 columns
    float4 as4 = *(const float4*)&at[h * (2 * OUT_DIM) + og];
    float4 ad4 = *(const float4*)&at[h * (2 * OUT_DIM) + OUT_DIM + og];

#pragma unroll
    for (int j = 0; j < 8; j++) {
        int n = n0 + warp * 8 + j;
        if (n < N_NODES) {
            float4 v = make_float4(acc[j][0], acc[j][1], acc[j][2], acc[j][3]);
            *(float4*)&g_Wh[(size_t)n * TOT_OUT + lane * 4] = v;

            // fused score: reduce v·a over the 8 lanes of this head
            float ps = v.x * as4.x + v.y * as4.y + v.z * as4.z + v.w * as4.w;
            float pd = v.x * ad4.x + v.y * ad4.y + v.z * ad4.z + v.w * ad4.w;
#pragma unroll
            for (int off = 4; off > 0; off >>= 1) {
                ps += __shfl_xor_sync(0xffffffffu, ps, off);
                pd += __shfl_xor_sync(0xffffffffu, pd, off);
            }
            if ((lane & 7) == 0) {
                g_ssrc[n * N_HEADS + h] = ps;
                g_sdst[n * N_HEADS + h] = pd;
            }
        }
    }
}

// ---------------- kernel 2: zero degree histogram ----------------------------
__global__ void init_kernel() {
    int i = blockIdx.x * blockDim.x + threadIdx.x;
    if (i < N_NODES) g_cnt[i] = 0;
}

// ---------------- kernel 3: in-degree histogram ------------------------------
// edge_index is int32 pairs (JAX x64 disabled downgrades int64 -> int32).
__global__ void hist_kernel(const int* __restrict__ ei) {
    int e2 = blockIdx.x * blockDim.x + threadIdx.x;   // handles 2 edges
    if (e2 * 2 >= N_EDGES) return;
    int4 p = ((const int4*)ei)[e2];   // (src0,dst0,src1,dst1)
    if ((unsigned)p.y < N_NODES) atomicAdd(&g_cnt[p.y], 1);
    if ((unsigned)p.w < N_NODES) atomicAdd(&g_cnt[p.w], 1);
}

// ---------------- kernel 4: exclusive scan of degrees -> offsets + cursors ---
#define SCAN_T 1024
__global__ void scan_kernel() {
    __shared__ int part[SCAN_T];
    const int t = threadIdx.x;
    const int chunk = (N_NODES + SCAN_T - 1) / SCAN_T;
    const int lo = t * chunk;
    const int hi = min(lo + chunk, N_NODES);

    int s = 0;
    for (int i = lo; i < hi; i++) s += g_cnt[i];
    part[t] = s;
    __syncthreads();

    for (int off = 1; off < SCAN_T; off <<= 1) {
        int v = (t >= off) ? part[t - off] : 0;
        __syncthreads();
        part[t] += v;
        __syncthreads();
    }

    int run = part[t] - s;
    for (int i = lo; i < hi; i++) {
        g_off[i] = run;
        g_cur[i] = run;
        run += g_cnt[i];
    }
    if (t == 0) g_off[N_NODES] = N_EDGES;
}

// ---------------- kernel 5: exp score + CSR scatter (fused) ------------------
__global__ void scatter_kernel(const int* __restrict__ ei) {
    int e = blockIdx.x * blockDim.x + threadIdx.x;
    if (e >= N_EDGES) return;
    int2 p = ((const int2*)ei)[e];
    int src = p.x, dst = p.y;
    if ((unsigned)src >= N_NODES || (unsigned)dst >= N_NODES) return;

    float4 ss = *(const float4*)&g_ssrc[src * N_HEADS];
    float4 sd = *(const float4*)&g_sdst[dst * N_HEADS];
    float4 v;
    v.x = __expf(lrelu(ss.x + sd.x));
    v.y = __expf(lrelu(ss.y + sd.y));
    v.z = __expf(lrelu(ss.z + sd.z));
    v.w = __expf(lrelu(ss.w + sd.w));

    int pos = atomicAdd(&g_cur[dst], 1);
    *(float4*)&g_exp[(size_t)pos * N_HEADS] = v;
    g_csr[pos] = make_int2(e, src);
}

// ---------------- kernel 6: gather (softmax-normalize + weighted sum) --------
// One warp per dst node. 32 lanes x float4 cover the 128-wide output row.
__global__ void gather_kernel(float* __restrict__ out_h,
                              float* __restrict__ out_alpha) {
    const int warp = threadIdx.x >> 5;
    const int lane = threadIdx.x & 31;
    const int d = blockIdx.x * 8 + warp;
    if (d >= N_NODES) return;

    const int beg = g_off[d];
    const int end = g_off[d + 1];

    // 1) sum of exp (coalesced: exp is CSR-ordered)
    float4 sum = make_float4(0.f, 0.f, 0.f, 0.f);
    for (int i = beg + lane; i < end; i += 32) {
        float4 ex = *(const float4*)&g_exp[(size_t)i * N_HEADS];
        sum.x += ex.x; sum.y += ex.y; sum.z += ex.z; sum.w += ex.w;
    }
#pragma unroll
    for (int off = 16; off > 0; off >>= 1) {
        sum.x += __shfl_xor_sync(0xffffffffu, sum.x, off);
        sum.y += __shfl_xor_sync(0xffffffffu, sum.y, off);
        sum.z += __shfl_xor_sync(0xffffffffu, sum.z, off);
        sum.w += __shfl_xor_sync(0xffffffffu, sum.w, off);
    }
    float4 rcp;
    rcp.x = 1.0f / (sum.x + 1e-9f);
    rcp.y = 1.0f / (sum.y + 1e-9f);
    rcp.z = 1.0f / (sum.z + 1e-9f);
    rcp.w = 1.0f / (sum.w + 1e-9f);

    // 2) accumulate alpha * Wh[src]; unrolled x4 for MLP
    float4 acc = make_float4(0.f, 0.f, 0.f, 0.f);
    const int hsel = lane >> 3;
    int i = beg;

    for (; i + 4 <= end; i += 4) {
        int2 c0 = g_csr[i];
        int2 c1 = g_csr[i + 1];
        int2 c2 = g_csr[i + 2];
        int2 c3 = g_csr[i + 3];
        float4 e0 = *(const float4*)&g_exp[(size_t)(i    ) * N_HEADS];
        float4 e1 = *(const float4*)&g_exp[(size_t)(i + 1) * N_HEADS];
        float4 e2 = *(const float4*)&g_exp[(size_t)(i + 2) * N_HEADS];
        float4 e3 = *(const float4*)&g_exp[(size_t)(i + 3) * N_HEADS];
        float4 w0 = *(const float4*)&g_Wh[(size_t)c0.y * TOT_OUT + lane * 4];
        float4 w1 = *(const float4*)&g_Wh[(size_t)c1.y * TOT_OUT + lane * 4];
        float4 w2 = *(const float4*)&g_Wh[(size_t)c2.y * TOT_OUT + lane * 4];
        float4 w3 = *(const float4*)&g_Wh[(size_t)c3.y * TOT_OUT + lane * 4];

        float4 a0 = make_float4(e0.x*rcp.x, e0.y*rcp.y, e0.z*rcp.z, e0.w*rcp.w);
        float4 a1 = make_float4(e1.x*rcp.x, e1.y*rcp.y, e1.z*rcp.z, e1.w*rcp.w);
        float4 a2 = make_float4(e2.x*rcp.x, e2.y*rcp.y, e2.z*rcp.z, e2.w*rcp.w);
        float4 a3 = make_float4(e3.x*rcp.x, e3.y*rcp.y, e3.z*rcp.z, e3.w*rcp.w);

        if (lane == 0) {
            *(float4*)&out_alpha[(size_t)c0.x * N_HEADS] = a0;
            *(float4*)&out_alpha[(size_t)c1.x * N_HEADS] = a1;
            *(float4*)&out_alpha[(size_t)c2.x * N_HEADS] = a2;
            *(float4*)&out_alpha[(size_t)c3.x * N_HEADS] = a3;
        }

        float s0 = (hsel == 0) ? a0.x : (hsel == 1) ? a0.y : (hsel == 2) ? a0.z : a0.w;
        float s1 = (hsel == 0) ? a1.x : (hsel == 1) ? a1.y : (hsel == 2) ? a1.z : a1.w;
        float s2 = (hsel == 0) ? a2.x : (hsel == 1) ? a2.y : (hsel == 2) ? a2.z : a2.w;
        float s3 = (hsel == 0) ? a3.x : (hsel == 1) ? a3.y : (hsel == 2) ? a3.z : a3.w;

        acc.x += s0 * w0.x + s1 * w1.x + s2 * w2.x + s3 * w3.x;
        acc.y += s0 * w0.y + s1 * w1.y + s2 * w2.y + s3 * w3.y;
        acc.z += s0 * w0.z + s1 * w1.z + s2 * w2.z + s3 * w3.z;
        acc.w += s0 * w0.w + s1 * w1.w + s2 * w2.w + s3 * w3.w;
    }
    for (; i < end; i++) {
        int2 ce = g_csr[i];
        float4 ex = *(const float4*)&g_exp[(size_t)i * N_HEADS];
        float4 a4 = make_float4(ex.x*rcp.x, ex.y*rcp.y, ex.z*rcp.z, ex.w*rcp.w);
        if (lane == 0) {
            *(float4*)&out_alpha[(size_t)ce.x * N_HEADS] = a4;
        }
        float4 wv = *(const float4*)&g_Wh[(size_t)ce.y * TOT_OUT + lane * 4];
        float a = (hsel == 0) ? a4.x : (hsel == 1) ? a4.y : (hsel == 2) ? a4.z : a4.w;
        acc.x += a * wv.x;
        acc.y += a * wv.y;
        acc.z += a * wv.z;
        acc.w += a * wv.w;
    }

    *(float4*)&out_h[(size_t)d * TOT_OUT + lane * 4] = acc;
}

// ---------------- launch -----------------------------------------------------
extern "C" void kernel_launch(void* const* d_in, const int* in_sizes, int n_in,
                              void* d_out, int out_size) {
    const float* x  = (const float*)d_in[0];
    const int*   ei = (const int*)d_in[1];
    const float* wt = (const float*)d_in[2];
    const float* at = (const float*)d_in[3];

    float* out_h     = (float*)d_out;                                   // [50000*128]
    float* out_alpha = (float*)d_out + (size_t)N_NODES * TOT_OUT;       // [1.6M*4]

    // 1. projection GEMM + fused attention-score epilogue
    gemm_kernel<<<(N_NODES + GEMM_NB - 1) / GEMM_NB, GEMM_TPB>>>(x, wt, at);

    // 2. zero degree histogram
    init_kernel<<<(N_NODES + 255) / 256, 256>>>();

    // 3. in-degree histogram (2 edges per thread)
    hist_kernel<<<(N_EDGES / 2 + 255) / 256, 256>>>(ei);

    // 4. scan degrees -> CSR offsets
    scan_kernel<<<1, SCAN_T>>>();

    // 5. exp scores + CSR scatter (fused)
    scatter_kernel<<<(N_EDGES + 255) / 256, 256>>>(ei);

    // 6. softmax-normalize + gather-accumulate per dst node
    gather_kernel<<<(N_NODES + 7) / 8, 256>>>(out_h, out_alpha);

    (void)in_sizes; (void)n_in; (void)out_size;
}

// round 6
// speedup vs baseline: 1.8587x; 1.2789x over previous
#include <cuda_runtime.h>
#include <cfloat>

// Problem constants (fixed shapes for this problem instance)
#define N_NODES  50000
#define N_EDGES  1600000
#define IN_DIM   128
#define OUT_DIM  32
#define N_HEADS  4
#define TOT_OUT  (N_HEADS * OUT_DIM)   // 128

#define SCAN_NB  ((N_NODES + 255) / 256)   // 196 blocks for level-1 scan

// ---------------- scratch (device globals; no allocations allowed) ----------
__device__ float g_Wh[(size_t)N_NODES * TOT_OUT];     // 25.6 MB
__device__ float g_ssrc[(size_t)N_NODES * N_HEADS];   // 800 KB
__device__ float g_sdst[(size_t)N_NODES * N_HEADS];   // 800 KB
__device__ float g_exp[(size_t)N_EDGES * N_HEADS];    // 25.6 MB  exp(e) in CSR order
__device__ int   g_cnt[N_NODES];                      // in-degree histogram
__device__ int   g_off[N_NODES + 1];                  // CSR offsets
__device__ int   g_cur[N_NODES];                      // scatter cursors
__device__ int   g_blk[SCAN_NB];                      // level-1 block totals
__device__ int   g_blkoff[SCAN_NB];                   // level-2 exclusive bases
__device__ int2  g_csr[(size_t)N_EDGES];              // (eid, src) per CSR slot

// ---------------- helpers ----------------------------------------------------
__device__ __forceinline__ float lrelu(float v) {
    return v > 0.0f ? v : 0.2f * v;
}

// block-wide inclusive scan of one int per thread (blockDim.x <= 256)
__device__ __forceinline__ int block_incl_scan(int v, int tid) {
    const int lane = tid & 31;
    const int w    = tid >> 5;
    int x = v;
#pragma unroll
    for (int off = 1; off < 32; off <<= 1) {
        int t = __shfl_up_sync(0xffffffffu, x, off);
        if (lane >= off) x += t;
    }
    __shared__ int wsum[8];
    if (lane == 31) wsum[w] = x;
    __syncthreads();
    if (w == 0) {
        int t = (lane < 8) ? wsum[lane] : 0;
#pragma unroll
        for (int off = 1; off < 8; off <<= 1) {
            int u = __shfl_up_sync(0xffffffffu, t, off);
            if (lane >= off) t += u;
        }
        if (lane < 8) wsum[lane] = t;
    }
    __syncthreads();
    if (w > 0) x += wsum[w - 1];
    return x;
}

// ---------------- kernel 1: Wh = x @ W, fused attention-score epilogue ------
#define GEMM_NB 64
#define GEMM_CK 32
#define GEMM_TPB 256

__global__ void gemm_kernel(const float* __restrict__ x,
                            const float* __restrict__ wt,
                            const float* __restrict__ at) {
    __shared__ float xs[GEMM_NB][GEMM_CK];
    __shared__ float ws[GEMM_CK][TOT_OUT];

    const int n0   = blockIdx.x * GEMM_NB;
    const int tid  = threadIdx.x;
    const int warp = tid >> 5;
    const int lane = tid & 31;
    const int h    = lane >> 3;        // head owned by this lane's 4 columns
    const int og   = (lane & 7) * 4;   // first out-col within head

    float acc[8][4];
#pragma unroll
    for (int j = 0; j < 8; j++) { acc[j][0]=0.f; acc[j][1]=0.f; acc[j][2]=0.f; acc[j][3]=0.f; }

    for (int k0 = 0; k0 < IN_DIM; k0 += GEMM_CK) {
        for (int idx = tid; idx < GEMM_CK * TOT_OUT; idx += GEMM_TPB) {
            int ki = idx >> 7;
            int c  = idx & 127;
            ws[ki][c] = wt[(c >> 5) * (IN_DIM * OUT_DIM) + (k0 + ki) * OUT_DIM + (c & 31)];
        }
        for (int idx = tid; idx < GEMM_NB * GEMM_CK; idx += GEMM_TPB) {
            int nl = idx / GEMM_CK;
            int ki = idx % GEMM_CK;
            int n  = n0 + nl;
            xs[nl][ki] = (n < N_NODES) ? x[(size_t)n * IN_DIM + k0 + ki] : 0.f;
        }
        __syncthreads();

#pragma unroll
        for (int ki = 0; ki < GEMM_CK; ki++) {
            float4 wv = *(const float4*)&ws[ki][lane * 4];
#pragma unroll
            for (int j = 0; j < 8; j++) {
                float xv = xs[warp * 8 + j][ki];
                acc[j][0] += xv * wv.x;
                acc[j][1] += xv * wv.y;
                acc[j][2] += xv * wv.z;
                acc[j][3] += xv * wv.w;
            }
        }
        __syncthreads();
    }

    // attention vectors for this lane's 4 columns
    float4 as4 = *(const float4*)&at[h * (2 * OUT_DIM) + og];
    float4 ad4 = *(const float4*)&at[h * (2 * OUT_DIM) + OUT_DIM + og];

#pragma unroll
    for (int j = 0; j < 8; j++) {
        int n = n0 + warp * 8 + j;
        if (n < N_NODES) {
            float4 v = make_float4(acc[j][0], acc[j][1], acc[j][2], acc[j][3]);
            *(float4*)&g_Wh[(size_t)n * TOT_OUT + lane * 4] = v;

            // fused score: reduce v·a over the 8 lanes of this head
            float ps = v.x * as4.x + v.y * as4.y + v.z * as4.z + v.w * as4.w;
            float pd = v.x * ad4.x + v.y * ad4.y + v.z * ad4.z + v.w * ad4.w;
#pragma unroll
            for (int off = 4; off > 0; off >>= 1) {
                ps += __shfl_xor_sync(0xffffffffu, ps, off);
                pd += __shfl_xor_sync(0xffffffffu, pd, off);
            }
            if ((lane & 7) == 0) {
                g_ssrc[n * N_HEADS + h] = ps;
                g_sdst[n * N_HEADS + h] = pd;
            }
        }
    }
}

// ---------------- kernel 2: zero degree histogram ----------------------------
__global__ void init_kernel() {
    int i = blockIdx.x * blockDim.x + threadIdx.x;
    if (i < N_NODES) g_cnt[i] = 0;
}

// ---------------- kernel 3: in-degree histogram ------------------------------
// edge_index is int32 pairs (JAX x64 disabled downgrades int64 -> int32).
__global__ void hist_kernel(const int* __restrict__ ei) {
    int e2 = blockIdx.x * blockDim.x + threadIdx.x;   // handles 2 edges
    if (e2 * 2 >= N_EDGES) return;
    int4 p = ((const int4*)ei)[e2];   // (src0,dst0,src1,dst1)
    if ((unsigned)p.y < N_NODES) atomicAdd(&g_cnt[p.y], 1);
    if ((unsigned)p.w < N_NODES) atomicAdd(&g_cnt[p.w], 1);
}

// ---------------- kernels 4a/4b/4c: two-level scan ---------------------------
// 4a: per-block exclusive prefix (pre-base) + block totals
__global__ void scan1_kernel() {
    const int tid = threadIdx.x;
    const int i   = blockIdx.x * 256 + tid;
    int v = (i < N_NODES) ? g_cnt[i] : 0;
    int incl = block_incl_scan(v, tid);
    if (i < N_NODES) g_off[i] = incl - v;         // exclusive, pre-base
    if (tid == 255) g_blk[blockIdx.x] = incl;     // block total
}

// 4b: scan the block totals (SCAN_NB=196 <= 256)
__global__ void scan2_kernel() {
    const int tid = threadIdx.x;
    int v = (tid < SCAN_NB) ? g_blk[tid] : 0;
    int incl = block_incl_scan(v, tid);
    if (tid < SCAN_NB) g_blkoff[tid] = incl - v;  // exclusive base
}

// 4c: add base, mirror into cursors
__global__ void scan3_kernel() {
    const int i = blockIdx.x * 256 + threadIdx.x;
    if (i < N_NODES) {
        int o = g_off[i] + g_blkoff[blockIdx.x];
        g_off[i] = o;
        g_cur[i] = o;
    }
    if (i == 0) g_off[N_NODES] = N_EDGES;
}

// ---------------- kernel 5: exp score + CSR scatter (fused) ------------------
__global__ void scatter_kernel(const int* __restrict__ ei) {
    int e = blockIdx.x * blockDim.x + threadIdx.x;
    if (e >= N_EDGES) return;
    int2 p = ((const int2*)ei)[e];
    int src = p.x, dst = p.y;
    if ((unsigned)src >= N_NODES || (unsigned)dst >= N_NODES) return;

    float4 ss = *(const float4*)&g_ssrc[src * N_HEADS];
    float4 sd = *(const float4*)&g_sdst[dst * N_HEADS];
    float4 v;
    v.x = __expf(lrelu(ss.x + sd.x));
    v.y = __expf(lrelu(ss.y + sd.y));
    v.z = __expf(lrelu(ss.z + sd.z));
    v.w = __expf(lrelu(ss.w + sd.w));

    int pos = atomicAdd(&g_cur[dst], 1);
    *(float4*)&g_exp[(size_t)pos * N_HEADS] = v;
    g_csr[pos] = make_int2(e, src);
}

// ---------------- kernel 6: gather (softmax-normalize + weighted sum) --------
// One warp per dst node. 32 lanes x float4 cover the 128-wide output row.
__global__ void gather_kernel(float* __restrict__ out_h,
                              float* __restrict__ out_alpha) {
    const int warp = threadIdx.x >> 5;
    const int lane = threadIdx.x & 31;
    const int d = blockIdx.x * 8 + warp;
    if (d >= N_NODES) return;

    const int beg = g_off[d];
    const int end = g_off[d + 1];

    // 1) sum of exp (coalesced: exp is CSR-ordered)
    float4 sum = make_float4(0.f, 0.f, 0.f, 0.f);
    for (int i = beg + lane; i < end; i += 32) {
        float4 ex = *(const float4*)&g_exp[(size_t)i * N_HEADS];
        sum.x += ex.x; sum.y += ex.y; sum.z += ex.z; sum.w += ex.w;
    }
#pragma unroll
    for (int off = 16; off > 0; off >>= 1) {
        sum.x += __shfl_xor_sync(0xffffffffu, sum.x, off);
        sum.y += __shfl_xor_sync(0xffffffffu, sum.y, off);
        sum.z += __shfl_xor_sync(0xffffffffu, sum.z, off);
        sum.w += __shfl_xor_sync(0xffffffffu, sum.w, off);
    }
    float4 rcp;
    rcp.x = 1.0f / (sum.x + 1e-9f);
    rcp.y = 1.0f / (sum.y + 1e-9f);
    rcp.z = 1.0f / (sum.z + 1e-9f);
    rcp.w = 1.0f / (sum.w + 1e-9f);

    // 2) accumulate alpha * Wh[src]; unrolled x4 for MLP
    float4 acc = make_float4(0.f, 0.f, 0.f, 0.f);
    const int hsel = lane >> 3;
    int i = beg;

    for (; i + 4 <= end; i += 4) {
        int2 c0 = g_csr[i];
        int2 c1 = g_csr[i + 1];
        int2 c2 = g_csr[i + 2];
        int2 c3 = g_csr[i + 3];
        float4 e0 = *(const float4*)&g_exp[(size_t)(i    ) * N_HEADS];
        float4 e1 = *(const float4*)&g_exp[(size_t)(i + 1) * N_HEADS];
        float4 e2 = *(const float4*)&g_exp[(size_t)(i + 2) * N_HEADS];
        float4 e3 = *(const float4*)&g_exp[(size_t)(i + 3) * N_HEADS];
        float4 w0 = *(const float4*)&g_Wh[(size_t)c0.y * TOT_OUT + lane * 4];
        float4 w1 = *(const float4*)&g_Wh[(size_t)c1.y * TOT_OUT + lane * 4];
        float4 w2 = *(const float4*)&g_Wh[(size_t)c2.y * TOT_OUT + lane * 4];
        float4 w3 = *(const float4*)&g_Wh[(size_t)c3.y * TOT_OUT + lane * 4];

        float4 a0 = make_float4(e0.x*rcp.x, e0.y*rcp.y, e0.z*rcp.z, e0.w*rcp.w);
        float4 a1 = make_float4(e1.x*rcp.x, e1.y*rcp.y, e1.z*rcp.z, e1.w*rcp.w);
        float4 a2 = make_float4(e2.x*rcp.x, e2.y*rcp.y, e2.z*rcp.z, e2.w*rcp.w);
        float4 a3 = make_float4(e3.x*rcp.x, e3.y*rcp.y, e3.z*rcp.z, e3.w*rcp.w);

        if (lane == 0) {
            *(float4*)&out_alpha[(size_t)c0.x * N_HEADS] = a0;
            *(float4*)&out_alpha[(size_t)c1.x * N_HEADS] = a1;
            *(float4*)&out_alpha[(size_t)c2.x * N_HEADS] = a2;
            *(float4*)&out_alpha[(size_t)c3.x * N_HEADS] = a3;
        }

        float s0 = (hsel == 0) ? a0.x : (hsel == 1) ? a0.y : (hsel == 2) ? a0.z : a0.w;
        float s1 = (hsel == 0) ? a1.x : (hsel == 1) ? a1.y : (hsel == 2) ? a1.z : a1.w;
        float s2 = (hsel == 0) ? a2.x : (hsel == 1) ? a2.y : (hsel == 2) ? a2.z : a2.w;
        float s3 = (hsel == 0) ? a3.x : (hsel == 1) ? a3.y : (hsel == 2) ? a3.z : a3.w;

        acc.x += s0 * w0.x + s1 * w1.x + s2 * w2.x + s3 * w3.x;
        acc.y += s0 * w0.y + s1 * w1.y + s2 * w2.y + s3 * w3.y;
        acc.z += s0 * w0.z + s1 * w1.z + s2 * w2.z + s3 * w3.z;
        acc.w += s0 * w0.w + s1 * w1.w + s2 * w2.w + s3 * w3.w;
    }
    for (; i < end; i++) {
        int2 ce = g_csr[i];
        float4 ex = *(const float4*)&g_exp[(size_t)i * N_HEADS];
        float4 a4 = make_float4(ex.x*rcp.x, ex.y*rcp.y, ex.z*rcp.z, ex.w*rcp.w);
        if (lane == 0) {
            *(float4*)&out_alpha[(size_t)ce.x * N_HEADS] = a4;
        }
        float4 wv = *(const float4*)&g_Wh[(size_t)ce.y * TOT_OUT + lane * 4];
        float a = (hsel == 0) ? a4.x : (hsel == 1) ? a4.y : (hsel == 2) ? a4.z : a4.w;
        acc.x += a * wv.x;
        acc.y += a * wv.y;
        acc.z += a * wv.z;
        acc.w += a * wv.w;
    }

    *(float4*)&out_h[(size_t)d * TOT_OUT + lane * 4] = acc;
}

// ---------------- launch -----------------------------------------------------
extern "C" void kernel_launch(void* const* d_in, const int* in_sizes, int n_in,
                              void* d_out, int out_size) {
    const float* x  = (const float*)d_in[0];
    const int*   ei = (const int*)d_in[1];
    const float* wt = (const float*)d_in[2];
    const float* at = (const float*)d_in[3];

    float* out_h     = (float*)d_out;                                   // [50000*128]
    float* out_alpha = (float*)d_out + (size_t)N_NODES * TOT_OUT;       // [1.6M*4]

    // 1. projection GEMM + fused attention-score epilogue
    gemm_kernel<<<(N_NODES + GEMM_NB - 1) / GEMM_NB, GEMM_TPB>>>(x, wt, at);

    // 2. zero degree histogram
    init_kernel<<<(N_NODES + 255) / 256, 256>>>();

    // 3. in-degree histogram (2 edges per thread)
    hist_kernel<<<(N_EDGES / 2 + 255) / 256, 256>>>(ei);

    // 4. two-level parallel scan -> CSR offsets + cursors
    scan1_kernel<<<SCAN_NB, 256>>>();
    scan2_kernel<<<1, 256>>>();
    scan3_kernel<<<SCAN_NB, 256>>>();

    // 5. exp scores + CSR scatter (fused)
    scatter_kernel<<<(N_EDGES + 255) / 256, 256>>>(ei);

    // 6. softmax-normalize + gather-accumulate per dst node
    gather_kernel<<<(N_NODES + 7) / 8, 256>>>(out_h, out_alpha);

    (void)in_sizes; (void)n_in; (void)out_size;
}

// round 9
// speedup vs baseline: 1.9041x; 1.0244x over previous
#include <cuda_runtime.h>
#include <cfloat>
#include <cstdint>

// Problem constants (fixed shapes for this problem instance)
#define N_NODES  50000
#define N_EDGES  1600000
#define IN_DIM   128
#define OUT_DIM  32
#define N_HEADS  4
#define TOT_OUT  (N_HEADS * OUT_DIM)   // 128

#define SCAN_NB  ((N_NODES + 255) / 256)   // 196 blocks for level-1 scan

// ---------------- scratch (device globals; no allocations allowed) ----------
__device__ float g_Wh[(size_t)N_NODES * TOT_OUT];     // 25.6 MB
__device__ float g_ssrc[(size_t)N_NODES * N_HEADS];   // 800 KB
__device__ float g_sdst[(size_t)N_NODES * N_HEADS];   // 800 KB
__device__ float g_exp[(size_t)N_EDGES * N_HEADS];    // 25.6 MB  exp(e) in CSR order
__device__ int   g_cnt[N_NODES];                      // in-degree histogram
__device__ int   g_off[N_NODES + 1];                  // CSR offsets
__device__ int   g_cur[N_NODES];                      // scatter cursors
__device__ int   g_blk[SCAN_NB];                      // level-1 block totals
__device__ int   g_blkoff[SCAN_NB];                   // level-2 exclusive bases
__device__ int2  g_csr[(size_t)N_EDGES];              // (eid, src) per CSR slot

// ---------------- helpers ----------------------------------------------------
__device__ __forceinline__ float lrelu(float v) {
    return v > 0.0f ? v : 0.2f * v;
}

__device__ __forceinline__ unsigned long long pack2(float a, float b) {
    unsigned long long r;
    asm("mov.b64 %0, {%1, %2};" : "=l"(r) : "f"(a), "f"(b));
    return r;
}
__device__ __forceinline__ void unpack2(unsigned long long v, float& a, float& b) {
    asm("mov.b64 {%0, %1}, %2;" : "=f"(a), "=f"(b) : "l"(v));
}
__device__ __forceinline__ void fma2(unsigned long long& d,
                                     unsigned long long a, unsigned long long b) {
    asm("fma.rn.f32x2 %0, %1, %2, %0;" : "+l"(d) : "l"(a), "l"(b));
}

// block-wide inclusive scan of one int per thread (blockDim.x <= 256)
__device__ __forceinline__ int block_incl_scan(int v, int tid) {
    const int lane = tid & 31;
    const int w    = tid >> 5;
    int x = v;
#pragma unroll
    for (int off = 1; off < 32; off <<= 1) {
        int t = __shfl_up_sync(0xffffffffu, x, off);
        if (lane >= off) x += t;
    }
    __shared__ int wsum[8];
    if (lane == 31) wsum[w] = x;
    __syncthreads();
    if (w == 0) {
        int t = (lane < 8) ? wsum[lane] : 0;
#pragma unroll
        for (int off = 1; off < 8; off <<= 1) {
            int u = __shfl_up_sync(0xffffffffu, t, off);
            if (lane >= off) t += u;
        }
        if (lane < 8) wsum[lane] = t;
    }
    __syncthreads();
    if (w > 0) x += wsum[w - 1];
    return x;
}

// ---------------- kernel 1: Wh = x @ W (f32x2), fused score epilogue ---------
// 128 nodes per block, 256 threads. Thread tile: 8 nodes x 8 cols.
//   cg = tid & 15  -> cols cg*8 .. cg*8+7  (head h = cg>>2)
//   ng = tid >> 4  -> nodes ng + 16*j, j = 0..7
#define GN   128
#define GK   32
#define XPAD 33

__global__ __launch_bounds__(256, 2)
void gemm_kernel(const float* __restrict__ x,
                 const float* __restrict__ wt,
                 const float* __restrict__ at) {
    __shared__ float xs[GN][XPAD];          // node-major, padded
    __shared__ float ws[GK][TOT_OUT];       // k-major weight chunk

    const int n0  = blockIdx.x * GN;
    const int tid = threadIdx.x;
    const int cg  = tid & 15;
    const int ng  = tid >> 4;

    unsigned long long acc[8][4];
#pragma unroll
    for (int j = 0; j < 8; j++)
#pragma unroll
        for (int p = 0; p < 4; p++) acc[j][p] = 0ull;

    for (int k0 = 0; k0 < IN_DIM; k0 += GK) {
        // weight chunk: ws[ki][c] = wt[(c>>5)*4096 + (k0+ki)*32 + (c&31)]
        for (int idx = tid; idx < GK * TOT_OUT; idx += 256) {
            int ki = idx >> 7;
            int c  = idx & 127;
            ws[ki][c] = wt[(c >> 5) * (IN_DIM * OUT_DIM) + (k0 + ki) * OUT_DIM + (c & 31)];
        }
        // x chunk: xs[row][ki] ; coalesced 128B-per-row loads
        for (int p = 0; p < 4; p++) {
            int flat = p * 1024 + tid * 4;     // 4096 floats per chunk
            int row  = flat >> 5;
            int col  = flat & 31;
            int n    = n0 + row;
            float4 v = (n < N_NODES)
                ? *(const float4*)&x[(size_t)n * IN_DIM + k0 + col]
                : make_float4(0.f, 0.f, 0.f, 0.f);
            xs[row][col]     = v.x;
            xs[row][col + 1] = v.y;
            xs[row][col + 2] = v.z;
            xs[row][col + 3] = v.w;
        }
        __syncthreads();

#pragma unroll
        for (int ki = 0; ki < GK; ki++) {
            unsigned long long wp[4];
            {
                float4 wa = *(const float4*)&ws[ki][cg * 8];
                float4 wb = *(const float4*)&ws[ki][cg * 8 + 4];
                wp[0] = pack2(wa.x, wa.y);
                wp[1] = pack2(wa.z, wa.w);
                wp[2] = pack2(wb.x, wb.y);
                wp[3] = pack2(wb.z, wb.w);
            }
#pragma unroll
            for (int j = 0; j < 8; j++) {
                float xv = xs[ng + 16 * j][ki];
                unsigned long long xp = pack2(xv, xv);
                fma2(acc[j][0], xp, wp[0]);
                fma2(acc[j][1], xp, wp[1]);
                fma2(acc[j][2], xp, wp[2]);
                fma2(acc[j][3], xp, wp[3]);
            }
        }
        __syncthreads();
    }

    // attention slices for this thread's 8 columns
    const int h  = cg >> 2;
    const int og = (cg & 3) * 8;
    float4 as0 = *(const float4*)&at[h * (2 * OUT_DIM) + og];
    float4 as1 = *(const float4*)&at[h * (2 * OUT_DIM) + og + 4];
    float4 ad0 = *(const float4*)&at[h * (2 * OUT_DIM) + OUT_DIM + og];
    float4 ad1 = *(const float4*)&at[h * (2 * OUT_DIM) + OUT_DIM + og + 4];

#pragma unroll
    for (int j = 0; j < 8; j++) {
        int n = n0 + ng + 16 * j;
        float v0, v1, v2, v3, v4, v5, v6, v7;
        unpack2(acc[j][0], v0, v1);
        unpack2(acc[j][1], v2, v3);
        unpack2(acc[j][2], v4, v5);
        unpack2(acc[j][3], v6, v7);

        float ps = v0*as0.x + v1*as0.y + v2*as0.z + v3*as0.w
                 + v4*as1.x + v5*as1.y + v6*as1.z + v7*as1.w;
        float pd = v0*ad0.x + v1*ad0.y + v2*ad0.z + v3*ad0.w
                 + v4*ad1.x + v5*ad1.y + v6*ad1.z + v7*ad1.w;
        // reduce across the 4 col-groups of this head (lane bits 0-1)
        ps += __shfl_xor_sync(0xffffffffu, ps, 1);
        pd += __shfl_xor_sync(0xffffffffu, pd, 1);
        ps += __shfl_xor_sync(0xffffffffu, ps, 2);
        pd += __shfl_xor_sync(0xffffffffu, pd, 2);

        if (n < N_NODES) {
            *(float4*)&g_Wh[(size_t)n * TOT_OUT + cg * 8]     = make_float4(v0, v1, v2, v3);
            *(float4*)&g_Wh[(size_t)n * TOT_OUT + cg * 8 + 4] = make_float4(v4, v5, v6, v7);
            if ((cg & 3) == 0) {
                g_ssrc[n * N_HEADS + h] = ps;
                g_sdst[n * N_HEADS + h] = pd;
            }
        }
    }
}

// ---------------- kernel 2: zero degree histogram ----------------------------
__global__ void init_kernel() {
    int i = blockIdx.x * blockDim.x + threadIdx.x;
    if (i < N_NODES) g_cnt[i] = 0;
}

// ---------------- kernel 3: in-degree histogram ------------------------------
// edge_index is int32 pairs (JAX x64 disabled downgrades int64 -> int32).
__global__ void hist_kernel(const int* __restrict__ ei) {
    int e2 = blockIdx.x * blockDim.x + threadIdx.x;   // handles 2 edges
    if (e2 * 2 >= N_EDGES) return;
    int4 p = ((const int4*)ei)[e2];   // (src0,dst0,src1,dst1)
    if ((unsigned)p.y < N_NODES) atomicAdd(&g_cnt[p.y], 1);
    if ((unsigned)p.w < N_NODES) atomicAdd(&g_cnt[p.w], 1);
}

// ---------------- kernels 4a/4b/4c: two-level scan ---------------------------
__global__ void scan1_kernel() {
    const int tid = threadIdx.x;
    const int i   = blockIdx.x * 256 + tid;
    int v = (i < N_NODES) ? g_cnt[i] : 0;
    int incl = block_incl_scan(v, tid);
    if (i < N_NODES) g_off[i] = incl - v;
    if (tid == 255) g_blk[blockIdx.x] = incl;
}

__global__ void scan2_kernel() {
    const int tid = threadIdx.x;
    int v = (tid < SCAN_NB) ? g_blk[tid] : 0;
    int incl = block_incl_scan(v, tid);
    if (tid < SCAN_NB) g_blkoff[tid] = incl - v;
}

__global__ void scan3_kernel() {
    const int i = blockIdx.x * 256 + threadIdx.x;
    if (i < N_NODES) {
        int o = g_off[i] + g_blkoff[blockIdx.x];
        g_off[i] = o;
        g_cur[i] = o;
    }
    if (i == 0) g_off[N_NODES] = N_EDGES;
}

// ---------------- kernel 5: exp score + CSR scatter (fused) ------------------
__global__ void scatter_kernel(const int* __restrict__ ei) {
    int e = blockIdx.x * blockDim.x + threadIdx.x;
    if (e >= N_EDGES) return;
    int2 p = ((const int2*)ei)[e];
    int src = p.x, dst = p.y;
    if ((unsigned)src >= N_NODES || (unsigned)dst >= N_NODES) return;

    float4 ss = *(const float4*)&g_ssrc[src * N_HEADS];
    float4 sd = *(const float4*)&g_sdst[dst * N_HEADS];
    float4 v;
    v.x = __expf(lrelu(ss.x + sd.x));
    v.y = __expf(lrelu(ss.y + sd.y));
    v.z = __expf(lrelu(ss.z + sd.z));
    v.w = __expf(lrelu(ss.w + sd.w));

    int pos = atomicAdd(&g_cur[dst], 1);
    *(float4*)&g_exp[(size_t)pos * N_HEADS] = v;
    g_csr[pos] = make_int2(e, src);
}

// ---------------- kernel 6: gather (softmax-normalize + weighted sum) --------
__global__ void gather_kernel(float* __restrict__ out_h,
                              float* __restrict__ out_alpha) {
    const int warp = threadIdx.x >> 5;
    const int lane = threadIdx.x & 31;
    const int d = blockIdx.x * 8 + warp;
    if (d >= N_NODES) return;

    const int beg = g_off[d];
    const int end = g_off[d + 1];

    // 1) sum of exp (coalesced: exp is CSR-ordered)
    float4 sum = make_float4(0.f, 0.f, 0.f, 0.f);
    for (int i = beg + lane; i < end; i += 32) {
        float4 ex = *(const float4*)&g_exp[(size_t)i * N_HEADS];
        sum.x += ex.x; sum.y += ex.y; sum.z += ex.z; sum.w += ex.w;
    }
#pragma unroll
    for (int off = 16; off > 0; off >>= 1) {
        sum.x += __shfl_xor_sync(0xffffffffu, sum.x, off);
        sum.y += __shfl_xor_sync(0xffffffffu, sum.y, off);
        sum.z += __shfl_xor_sync(0xffffffffu, sum.z, off);
        sum.w += __shfl_xor_sync(0xffffffffu, sum.w, off);
    }
    float4 rcp;
    rcp.x = 1.0f / (sum.x + 1e-9f);
    rcp.y = 1.0f / (sum.y + 1e-9f);
    rcp.z = 1.0f / (sum.z + 1e-9f);
    rcp.w = 1.0f / (sum.w + 1e-9f);

    // 2) accumulate alpha * Wh[src]; unrolled x4 for MLP
    float4 acc = make_float4(0.f, 0.f, 0.f, 0.f);
    const int hsel = lane >> 3;
    int i = beg;

    for (; i + 4 <= end; i += 4) {
        int2 c0 = g_csr[i];
        int2 c1 = g_csr[i + 1];
        int2 c2 = g_csr[i + 2];
        int2 c3 = g_csr[i + 3];
        float4 e0 = *(const float4*)&g_exp[(size_t)(i    ) * N_HEADS];
        float4 e1 = *(const float4*)&g_exp[(size_t)(i + 1) * N_HEADS];
        float4 e2 = *(const float4*)&g_exp[(size_t)(i + 2) * N_HEADS];
        float4 e3 = *(const float4*)&g_exp[(size_t)(i + 3) * N_HEADS];
        float4 w0 = *(const float4*)&g_Wh[(size_t)c0.y * TOT_OUT + lane * 4];
        float4 w1 = *(const float4*)&g_Wh[(size_t)c1.y * TOT_OUT + lane * 4];
        float4 w2 = *(const float4*)&g_Wh[(size_t)c2.y * TOT_OUT + lane * 4];
        float4 w3 = *(const float4*)&g_Wh[(size_t)c3.y * TOT_OUT + lane * 4];

        float4 a0 = make_float4(e0.x*rcp.x, e0.y*rcp.y, e0.z*rcp.z, e0.w*rcp.w);
        float4 a1 = make_float4(e1.x*rcp.x, e1.y*rcp.y, e1.z*rcp.z, e1.w*rcp.w);
        float4 a2 = make_float4(e2.x*rcp.x, e2.y*rcp.y, e2.z*rcp.z, e2.w*rcp.w);
        float4 a3 = make_float4(e3.x*rcp.x, e3.y*rcp.y, e3.z*rcp.z, e3.w*rcp.w);

        // distribute the 4 alpha stores over lanes 0..3 (all lanes hold c/a)
        if (lane < 4) {
            int   eid = (lane == 0) ? c0.x : (lane == 1) ? c1.x : (lane == 2) ? c2.x : c3.x;
            float4 av = (lane == 0) ? a0   : (lane == 1) ? a1   : (lane == 2) ? a2   : a3;
            *(float4*)&out_alpha[(size_t)eid * N_HEADS] = av;
        }

        float s0 = (hsel == 0) ? a0.x : (hsel == 1) ? a0.y : (hsel == 2) ? a0.z : a0.w;
        float s1 = (hsel == 0) ? a1.x : (hsel == 1) ? a1.y : (hsel == 2) ? a1.z : a1.w;
        float s2 = (hsel == 0) ? a2.x : (hsel == 1) ? a2.y : (hsel == 2) ? a2.z : a2.w;
        float s3 = (hsel == 0) ? a3.x : (hsel == 1) ? a3.y : (hsel == 2) ? a3.z : a3.w;

        acc.x += s0 * w0.x + s1 * w1.x + s2 * w2.x + s3 * w3.x;
        acc.y += s0 * w0.y + s1 * w1.y + s2 * w2.y + s3 * w3.y;
        acc.z += s0 * w0.z + s1 * w1.z + s2 * w2.z + s3 * w3.z;
        acc.w += s0 * w0.w + s1 * w1.w + s2 * w2.w + s3 * w3.w;
    }
    for (; i < end; i++) {
        int2 ce = g_csr[i];
        float4 ex = *(const float4*)&g_exp[(size_t)i * N_HEADS];
        float4 a4 = make_float4(ex.x*rcp.x, ex.y*rcp.y, ex.z*rcp.z, ex.w*rcp.w);
        if (lane == 0) {
            *(float4*)&out_alpha[(size_t)ce.x * N_HEADS] = a4;
        }
        float4 wv = *(const float4*)&g_Wh[(size_t)ce.y * TOT_OUT + lane * 4];
        float a = (hsel == 0) ? a4.x : (hsel == 1) ? a4.y : (hsel == 2) ? a4.z : a4.w;
        acc.x += a * wv.x;
        acc.y += a * wv.y;
        acc.z += a * wv.z;
        acc.w += a * wv.w;
    }

    *(float4*)&out_h[(size_t)d * TOT_OUT + lane * 4] = acc;
}

// ---------------- launch -----------------------------------------------------
extern "C" void kernel_launch(void* const* d_in, const int* in_sizes, int n_in,
                              void* d_out, int out_size) {
    const float* x  = (const float*)d_in[0];
    const int*   ei = (const int*)d_in[1];
    const float* wt = (const float*)d_in[2];
    const float* at = (const float*)d_in[3];

    float* out_h     = (float*)d_out;                                   // [50000*128]
    float* out_alpha = (float*)d_out + (size_t)N_NODES * TOT_OUT;       // [1.6M*4]

    // 1. projection GEMM (f32x2 packed) + fused attention-score epilogue
    gemm_kernel<<<(N_NODES + GN - 1) / GN, 256>>>(x, wt, at);

    // 2. zero degree histogram
    init_kernel<<<(N_NODES + 255) / 256, 256>>>();

    // 3. in-degree histogram (2 edges per thread)
    hist_kernel<<<(N_EDGES / 2 + 255) / 256, 256>>>(ei);

    // 4. two-level parallel scan -> CSR offsets + cursors
    scan1_kernel<<<SCAN_NB, 256>>>();
    scan2_kernel<<<1, 256>>>();
    scan3_kernel<<<SCAN_NB, 256>>>();

    // 5. exp scores + CSR scatter (fused)
    scatter_kernel<<<(N_EDGES + 255) / 256, 256>>>(ei);

    // 6. softmax-normalize + gather-accumulate per dst node
    gather_kernel<<<(N_NODES + 7) / 8, 256>>>(out_h, out_alpha);

    (void)in_sizes; (void)n_in; (void)out_size;
}

// round 10
// speedup vs baseline: 1.9270x; 1.0120x over previous
#include <cuda_runtime.h>
#include <cfloat>
#include <cstdint>

// Problem constants (fixed shapes for this problem instance)
#define N_NODES  50000
#define N_EDGES  1600000
#define IN_DIM   128
#define OUT_DIM  32
#define N_HEADS  4
#define TOT_OUT  (N_HEADS * OUT_DIM)   // 128

#define SCAN_NB  ((N_NODES + 255) / 256)   // 196 blocks for level-1 scan

// ---------------- scratch (device globals; no allocations allowed) ----------
__device__ float g_Wh[(size_t)N_NODES * TOT_OUT];     // 25.6 MB
__device__ float g_ssrc[(size_t)N_NODES * N_HEADS];   // 800 KB
__device__ float g_sdst[(size_t)N_NODES * N_HEADS];   // 800 KB
__device__ float g_sum[(size_t)N_NODES * N_HEADS];    // 800 KB softmax denominators
__device__ float g_exp[(size_t)N_EDGES * N_HEADS];    // 25.6 MB  exp(e) in CSR order
__device__ int   g_cnt[N_NODES];                      // in-degree histogram
__device__ int   g_off[N_NODES + 1];                  // CSR offsets
__device__ int   g_cur[N_NODES];                      // scatter cursors
__device__ int   g_blk[SCAN_NB];                      // level-1 block totals
__device__ int   g_blkoff[SCAN_NB];                   // level-2 exclusive bases
__device__ int2  g_csr[(size_t)N_EDGES];              // (eid, src) per CSR slot

// ---------------- helpers ----------------------------------------------------
__device__ __forceinline__ float lrelu(float v) {
    return v > 0.0f ? v : 0.2f * v;
}

__device__ __forceinline__ void redAdd4(float* p, float4 v) {
    asm volatile("red.global.add.v4.f32 [%0], {%1,%2,%3,%4};"
                 :: "l"(p), "f"(v.x), "f"(v.y), "f"(v.z), "f"(v.w) : "memory");
}

__device__ __forceinline__ unsigned long long pack2(float a, float b) {
    unsigned long long r;
    asm("mov.b64 %0, {%1, %2};" : "=l"(r) : "f"(a), "f"(b));
    return r;
}
__device__ __forceinline__ void unpack2(unsigned long long v, float& a, float& b) {
    asm("mov.b64 {%0, %1}, %2;" : "=f"(a), "=f"(b) : "l"(v));
}
__device__ __forceinline__ void fma2(unsigned long long& d,
                                     unsigned long long a, unsigned long long b) {
    asm("fma.rn.f32x2 %0, %1, %2, %0;" : "+l"(d) : "l"(a), "l"(b));
}

// block-wide inclusive scan of one int per thread (blockDim.x <= 256)
__device__ __forceinline__ int block_incl_scan(int v, int tid) {
    const int lane = tid & 31;
    const int w    = tid >> 5;
    int x = v;
#pragma unroll
    for (int off = 1; off < 32; off <<= 1) {
        int t = __shfl_up_sync(0xffffffffu, x, off);
        if (lane >= off) x += t;
    }
    __shared__ int wsum[8];
    if (lane == 31) wsum[w] = x;
    __syncthreads();
    if (w == 0) {
        int t = (lane < 8) ? wsum[lane] : 0;
#pragma unroll
        for (int off = 1; off < 8; off <<= 1) {
            int u = __shfl_up_sync(0xffffffffu, t, off);
            if (lane >= off) t += u;
        }
        if (lane < 8) wsum[lane] = t;
    }
    __syncthreads();
    if (w > 0) x += wsum[w - 1];
    return x;
}

// ---------------- kernel 1: Wh = x @ W (f32x2), fused score epilogue ---------
// 128 nodes per block, 256 threads. Thread tile: 8 nodes x 8 cols.
#define GN   128
#define GK   32
#define XPAD 33

__global__ __launch_bounds__(256, 2)
void gemm_kernel(const float* __restrict__ x,
                 const float* __restrict__ wt,
                 const float* __restrict__ at) {
    __shared__ float xs[GN][XPAD];          // node-major, padded
    __shared__ float ws[GK][TOT_OUT];       // k-major weight chunk

    const int n0  = blockIdx.x * GN;
    const int tid = threadIdx.x;
    const int cg  = tid & 15;
    const int ng  = tid >> 4;

    unsigned long long acc[8][4];
#pragma unroll
    for (int j = 0; j < 8; j++)
#pragma unroll
        for (int p = 0; p < 4; p++) acc[j][p] = 0ull;

    for (int k0 = 0; k0 < IN_DIM; k0 += GK) {
        for (int idx = tid; idx < GK * TOT_OUT; idx += 256) {
            int ki = idx >> 7;
            int c  = idx & 127;
            ws[ki][c] = wt[(c >> 5) * (IN_DIM * OUT_DIM) + (k0 + ki) * OUT_DIM + (c & 31)];
        }
        for (int p = 0; p < 4; p++) {
            int flat = p * 1024 + tid * 4;
            int row  = flat >> 5;
            int col  = flat & 31;
            int n    = n0 + row;
            float4 v = (n < N_NODES)
                ? *(const float4*)&x[(size_t)n * IN_DIM + k0 + col]
                : make_float4(0.f, 0.f, 0.f, 0.f);
            xs[row][col]     = v.x;
            xs[row][col + 1] = v.y;
            xs[row][col + 2] = v.z;
            xs[row][col + 3] = v.w;
        }
        __syncthreads();

#pragma unroll
        for (int ki = 0; ki < GK; ki++) {
            unsigned long long wp[4];
            {
                float4 wa = *(const float4*)&ws[ki][cg * 8];
                float4 wb = *(const float4*)&ws[ki][cg * 8 + 4];
                wp[0] = pack2(wa.x, wa.y);
                wp[1] = pack2(wa.z, wa.w);
                wp[2] = pack2(wb.x, wb.y);
                wp[3] = pack2(wb.z, wb.w);
            }
#pragma unroll
            for (int j = 0; j < 8; j++) {
                float xv = xs[ng + 16 * j][ki];
                unsigned long long xp = pack2(xv, xv);
                fma2(acc[j][0], xp, wp[0]);
                fma2(acc[j][1], xp, wp[1]);
                fma2(acc[j][2], xp, wp[2]);
                fma2(acc[j][3], xp, wp[3]);
            }
        }
        __syncthreads();
    }

    const int h  = cg >> 2;
    const int og = (cg & 3) * 8;
    float4 as0 = *(const float4*)&at[h * (2 * OUT_DIM) + og];
    float4 as1 = *(const float4*)&at[h * (2 * OUT_DIM) + og + 4];
    float4 ad0 = *(const float4*)&at[h * (2 * OUT_DIM) + OUT_DIM + og];
    float4 ad1 = *(const float4*)&at[h * (2 * OUT_DIM) + OUT_DIM + og + 4];

#pragma unroll
    for (int j = 0; j < 8; j++) {
        int n = n0 + ng + 16 * j;
        float v0, v1, v2, v3, v4, v5, v6, v7;
        unpack2(acc[j][0], v0, v1);
        unpack2(acc[j][1], v2, v3);
        unpack2(acc[j][2], v4, v5);
        unpack2(acc[j][3], v6, v7);

        float ps = v0*as0.x + v1*as0.y + v2*as0.z + v3*as0.w
                 + v4*as1.x + v5*as1.y + v6*as1.z + v7*as1.w;
        float pd = v0*ad0.x + v1*ad0.y + v2*ad0.z + v3*ad0.w
                 + v4*ad1.x + v5*ad1.y + v6*ad1.z + v7*ad1.w;
        ps += __shfl_xor_sync(0xffffffffu, ps, 1);
        pd += __shfl_xor_sync(0xffffffffu, pd, 1);
        ps += __shfl_xor_sync(0xffffffffu, ps, 2);
        pd += __shfl_xor_sync(0xffffffffu, pd, 2);

        if (n < N_NODES) {
            *(float4*)&g_Wh[(size_t)n * TOT_OUT + cg * 8]     = make_float4(v0, v1, v2, v3);
            *(float4*)&g_Wh[(size_t)n * TOT_OUT + cg * 8 + 4] = make_float4(v4, v5, v6, v7);
            if ((cg & 3) == 0) {
                g_ssrc[n * N_HEADS + h] = ps;
                g_sdst[n * N_HEADS + h] = pd;
            }
        }
    }
}

// ---------------- kernel 2: init (zero histogram + softmax sums) -------------
__global__ void init_kernel() {
    int i = blockIdx.x * blockDim.x + threadIdx.x;
    if (i < N_NODES) g_cnt[i] = 0;
    if (i < N_NODES * N_HEADS) g_sum[i] = 0.0f;
}

// ---------------- kernel 3: in-degree histogram ------------------------------
// edge_index is int32 pairs (JAX x64 disabled downgrades int64 -> int32).
__global__ void hist_kernel(const int* __restrict__ ei) {
    int e2 = blockIdx.x * blockDim.x + threadIdx.x;   // handles 2 edges
    if (e2 * 2 >= N_EDGES) return;
    int4 p = ((const int4*)ei)[e2];   // (src0,dst0,src1,dst1)
    if ((unsigned)p.y < N_NODES) atomicAdd(&g_cnt[p.y], 1);
    if ((unsigned)p.w < N_NODES) atomicAdd(&g_cnt[p.w], 1);
}

// ---------------- kernels 4a/4b/4c: two-level scan ---------------------------
__global__ void scan1_kernel() {
    const int tid = threadIdx.x;
    const int i   = blockIdx.x * 256 + tid;
    int v = (i < N_NODES) ? g_cnt[i] : 0;
    int incl = block_incl_scan(v, tid);
    if (i < N_NODES) g_off[i] = incl - v;
    if (tid == 255) g_blk[blockIdx.x] = incl;
}

__global__ void scan2_kernel() {
    const int tid = threadIdx.x;
    int v = (tid < SCAN_NB) ? g_blk[tid] : 0;
    int incl = block_incl_scan(v, tid);
    if (tid < SCAN_NB) g_blkoff[tid] = incl - v;
}

__global__ void scan3_kernel() {
    const int i = blockIdx.x * 256 + threadIdx.x;
    if (i < N_NODES) {
        int o = g_off[i] + g_blkoff[blockIdx.x];
        g_off[i] = o;
        g_cur[i] = o;
    }
    if (i == 0) g_off[N_NODES] = N_EDGES;
}

// ---------------- kernel 5: exp score + CSR scatter + softmax sum ------------
__global__ void scatter_kernel(const int* __restrict__ ei) {
    int e = blockIdx.x * blockDim.x + threadIdx.x;
    if (e >= N_EDGES) return;
    int2 p = ((const int2*)ei)[e];
    int src = p.x, dst = p.y;
    if ((unsigned)src >= N_NODES || (unsigned)dst >= N_NODES) return;

    float4 ss = *(const float4*)&g_ssrc[src * N_HEADS];
    float4 sd = *(const float4*)&g_sdst[dst * N_HEADS];
    float4 v;
    v.x = __expf(lrelu(ss.x + sd.x));
    v.y = __expf(lrelu(ss.y + sd.y));
    v.z = __expf(lrelu(ss.z + sd.z));
    v.w = __expf(lrelu(ss.w + sd.w));

    int pos = atomicAdd(&g_cur[dst], 1);
    *(float4*)&g_exp[(size_t)pos * N_HEADS] = v;
    g_csr[pos] = make_int2(e, src);
    redAdd4(&g_sum[dst * N_HEADS], v);
}

// ---------------- kernel 6: gather (single pass: normalize + weighted sum) ---
__global__ void gather_kernel(float* __restrict__ out_h,
                              float* __restrict__ out_alpha) {
    const int warp = threadIdx.x >> 5;
    const int lane = threadIdx.x & 31;
    const int d = blockIdx.x * 8 + warp;
    if (d >= N_NODES) return;

    const int beg = g_off[d];
    const int end = g_off[d + 1];

    float4 s4 = *(const float4*)&g_sum[d * N_HEADS];
    float4 rcp;
    rcp.x = 1.0f / (s4.x + 1e-9f);
    rcp.y = 1.0f / (s4.y + 1e-9f);
    rcp.z = 1.0f / (s4.z + 1e-9f);
    rcp.w = 1.0f / (s4.w + 1e-9f);

    float4 acc = make_float4(0.f, 0.f, 0.f, 0.f);
    const int hsel = lane >> 3;
    int i = beg;

    for (; i + 4 <= end; i += 4) {
        int2 c0 = g_csr[i];
        int2 c1 = g_csr[i + 1];
        int2 c2 = g_csr[i + 2];
        int2 c3 = g_csr[i + 3];
        float4 e0 = *(const float4*)&g_exp[(size_t)(i    ) * N_HEADS];
        float4 e1 = *(const float4*)&g_exp[(size_t)(i + 1) * N_HEADS];
        float4 e2 = *(const float4*)&g_exp[(size_t)(i + 2) * N_HEADS];
        float4 e3 = *(const float4*)&g_exp[(size_t)(i + 3) * N_HEADS];
        float4 w0 = *(const float4*)&g_Wh[(size_t)c0.y * TOT_OUT + lane * 4];
        float4 w1 = *(const float4*)&g_Wh[(size_t)c1.y * TOT_OUT + lane * 4];
        float4 w2 = *(const float4*)&g_Wh[(size_t)c2.y * TOT_OUT + lane * 4];
        float4 w3 = *(const float4*)&g_Wh[(size_t)c3.y * TOT_OUT + lane * 4];

        float4 a0 = make_float4(e0.x*rcp.x, e0.y*rcp.y, e0.z*rcp.z, e0.w*rcp.w);
        float4 a1 = make_float4(e1.x*rcp.x, e1.y*rcp.y, e1.z*rcp.z, e1.w*rcp.w);
        float4 a2 = make_float4(e2.x*rcp.x, e2.y*rcp.y, e2.z*rcp.z, e2.w*rcp.w);
        float4 a3 = make_float4(e3.x*rcp.x, e3.y*rcp.y, e3.z*rcp.z, e3.w*rcp.w);

        // distribute the 4 alpha stores over lanes 0..3 (all lanes hold c/a)
        if (lane < 4) {
            int   eid = (lane == 0) ? c0.x : (lane == 1) ? c1.x : (lane == 2) ? c2.x : c3.x;
            float4 av = (lane == 0) ? a0   : (lane == 1) ? a1   : (lane == 2) ? a2   : a3;
            *(float4*)&out_alpha[(size_t)eid * N_HEADS] = av;
        }

        float s0 = (hsel == 0) ? a0.x : (hsel == 1) ? a0.y : (hsel == 2) ? a0.z : a0.w;
        float s1 = (hsel == 0) ? a1.x : (hsel == 1) ? a1.y : (hsel == 2) ? a1.z : a1.w;
        float s2 = (hsel == 0) ? a2.x : (hsel == 1) ? a2.y : (hsel == 2) ? a2.z : a2.w;
        float s3 = (hsel == 0) ? a3.x : (hsel == 1) ? a3.y : (hsel == 2) ? a3.z : a3.w;

        acc.x += s0 * w0.x + s1 * w1.x + s2 * w2.x + s3 * w3.x;
        acc.y += s0 * w0.y + s1 * w1.y + s2 * w2.y + s3 * w3.y;
        acc.z += s0 * w0.z + s1 * w1.z + s2 * w2.z + s3 * w3.z;
        acc.w += s0 * w0.w + s1 * w1.w + s2 * w2.w + s3 * w3.w;
    }
    for (; i < end; i++) {
        int2 ce = g_csr[i];
        float4 ex = *(const float4*)&g_exp[(size_t)i * N_HEADS];
        float4 a4 = make_float4(ex.x*rcp.x, ex.y*rcp.y, ex.z*rcp.z, ex.w*rcp.w);
        if (lane == 0) {
            *(float4*)&out_alpha[(size_t)ce.x * N_HEADS] = a4;
        }
        float4 wv = *(const float4*)&g_Wh[(size_t)ce.y * TOT_OUT + lane * 4];
        float a = (hsel == 0) ? a4.x : (hsel == 1) ? a4.y : (hsel == 2) ? a4.z : a4.w;
        acc.x += a * wv.x;
        acc.y += a * wv.y;
        acc.z += a * wv.z;
        acc.w += a * wv.w;
    }

    *(float4*)&out_h[(size_t)d * TOT_OUT + lane * 4] = acc;
}

// ---------------- launch -----------------------------------------------------
extern "C" void kernel_launch(void* const* d_in, const int* in_sizes, int n_in,
                              void* d_out, int out_size) {
    const float* x  = (const float*)d_in[0];
    const int*   ei = (const int*)d_in[1];
    const float* wt = (const float*)d_in[2];
    const float* at = (const float*)d_in[3];

    float* out_h     = (float*)d_out;                                   // [50000*128]
    float* out_alpha = (float*)d_out + (size_t)N_NODES * TOT_OUT;       // [1.6M*4]

    // 1. projection GEMM (f32x2 packed) + fused attention-score epilogue
    gemm_kernel<<<(N_NODES + GN - 1) / GN, 256>>>(x, wt, at);

    // 2. zero histogram + softmax sums
    init_kernel<<<(N_NODES * N_HEADS + 255) / 256, 256>>>();

    // 3. in-degree histogram (2 edges per thread)
    hist_kernel<<<(N_EDGES / 2 + 255) / 256, 256>>>(ei);

    // 4. two-level parallel scan -> CSR offsets + cursors
    scan1_kernel<<<SCAN_NB, 256>>>();
    scan2_kernel<<<1, 256>>>();
    scan3_kernel<<<SCAN_NB, 256>>>();

    // 5. exp scores + CSR scatter + softmax-sum accumulation (fused)
    scatter_kernel<<<(N_EDGES + 255) / 256, 256>>>(ei);

    // 6. single-pass normalize + gather-accumulate per dst node
    gather_kernel<<<(N_NODES + 7) / 8, 256>>>(out_h, out_alpha);

    (void)in_sizes; (void)n_in; (void)out_size;
}

// round 11
// speedup vs baseline: 2.3352x; 1.2118x over previous
#include <cuda_runtime.h>
#include <cfloat>
#include <cstdint>

// Problem constants (fixed shapes for this problem instance)
#define N_NODES  50000
#define N_EDGES  1600000
#define IN_DIM   128
#define OUT_DIM  32
#define N_HEADS  4
#define TOT_OUT  (N_HEADS * OUT_DIM)   // 128

#define SCAN_NB  ((N_NODES + 255) / 256)   // 196 blocks for level-1 scan

// ---------------- scratch (device globals; no allocations allowed) ----------
__device__ float g_Wh[(size_t)N_NODES * TOT_OUT];     // 25.6 MB
__device__ float g_ssrc[(size_t)N_NODES * N_HEADS];   // 800 KB
__device__ float g_sdst[(size_t)N_NODES * N_HEADS];   // 800 KB
__device__ float g_sum[(size_t)N_NODES * N_HEADS];    // 800 KB softmax denominators
__device__ int   g_cnt[N_NODES];                      // in-degree histogram
__device__ int   g_off[N_NODES + 1];                  // CSR offsets
__device__ int   g_cur[N_NODES];                      // scatter cursors
__device__ int   g_blk[SCAN_NB];                      // level-1 block totals
__device__ int   g_blkoff[SCAN_NB];                   // level-2 exclusive bases
__device__ int   g_src[(size_t)N_EDGES];              // src per CSR slot (6.4 MB)

// ---------------- helpers ----------------------------------------------------
__device__ __forceinline__ float lrelu(float v) {
    return v > 0.0f ? v : 0.2f * v;
}

__device__ __forceinline__ void redAdd4(float* p, float4 v) {
    asm volatile("red.global.add.v4.f32 [%0], {%1,%2,%3,%4};"
                 :: "l"(p), "f"(v.x), "f"(v.y), "f"(v.z), "f"(v.w) : "memory");
}

__device__ __forceinline__ unsigned long long pack2(float a, float b) {
    unsigned long long r;
    asm("mov.b64 %0, {%1, %2};" : "=l"(r) : "f"(a), "f"(b));
    return r;
}
__device__ __forceinline__ void unpack2(unsigned long long v, float& a, float& b) {
    asm("mov.b64 {%0, %1}, %2;" : "=f"(a), "=f"(b) : "l"(v));
}
__device__ __forceinline__ void fma2(unsigned long long& d,
                                     unsigned long long a, unsigned long long b) {
    asm("fma.rn.f32x2 %0, %1, %2, %0;" : "+l"(d) : "l"(a), "l"(b));
}

// block-wide inclusive scan of one int per thread (blockDim.x <= 256)
__device__ __forceinline__ int block_incl_scan(int v, int tid) {
    const int lane = tid & 31;
    const int w    = tid >> 5;
    int x = v;
#pragma unroll
    for (int off = 1; off < 32; off <<= 1) {
        int t = __shfl_up_sync(0xffffffffu, x, off);
        if (lane >= off) x += t;
    }
    __shared__ int wsum[8];
    if (lane == 31) wsum[w] = x;
    __syncthreads();
    if (w == 0) {
        int t = (lane < 8) ? wsum[lane] : 0;
#pragma unroll
        for (int off = 1; off < 8; off <<= 1) {
            int u = __shfl_up_sync(0xffffffffu, t, off);
            if (lane >= off) t += u;
        }
        if (lane < 8) wsum[lane] = t;
    }
    __syncthreads();
    if (w > 0) x += wsum[w - 1];
    return x;
}

// ---------------- kernel 1: Wh = x @ W (f32x2), fused score epilogue ---------
// 128 nodes per block, 256 threads. Thread tile: 8 nodes x 8 cols.
#define GN   128
#define GK   32
#define XPAD 33

__global__ __launch_bounds__(256, 2)
void gemm_kernel(const float* __restrict__ x,
                 const float* __restrict__ wt,
                 const float* __restrict__ at) {
    __shared__ float xs[GN][XPAD];          // node-major, padded
    __shared__ float ws[GK][TOT_OUT];       // k-major weight chunk

    const int n0  = blockIdx.x * GN;
    const int tid = threadIdx.x;
    const int cg  = tid & 15;
    const int ng  = tid >> 4;

    unsigned long long acc[8][4];
#pragma unroll
    for (int j = 0; j < 8; j++)
#pragma unroll
        for (int p = 0; p < 4; p++) acc[j][p] = 0ull;

    for (int k0 = 0; k0 < IN_DIM; k0 += GK) {
        for (int idx = tid; idx < GK * TOT_OUT; idx += 256) {
            int ki = idx >> 7;
            int c  = idx & 127;
            ws[ki][c] = wt[(c >> 5) * (IN_DIM * OUT_DIM) + (k0 + ki) * OUT_DIM + (c & 31)];
        }
        for (int p = 0; p < 4; p++) {
            int flat = p * 1024 + tid * 4;
            int row  = flat >> 5;
            int col  = flat & 31;
            int n    = n0 + row;
            float4 v = (n < N_NODES)
                ? *(const float4*)&x[(size_t)n * IN_DIM + k0 + col]
                : make_float4(0.f, 0.f, 0.f, 0.f);
            xs[row][col]     = v.x;
            xs[row][col + 1] = v.y;
            xs[row][col + 2] = v.z;
            xs[row][col + 3] = v.w;
        }
        __syncthreads();

#pragma unroll
        for (int ki = 0; ki < GK; ki++) {
            unsigned long long wp[4];
            {
                float4 wa = *(const float4*)&ws[ki][cg * 8];
                float4 wb = *(const float4*)&ws[ki][cg * 8 + 4];
                wp[0] = pack2(wa.x, wa.y);
                wp[1] = pack2(wa.z, wa.w);
                wp[2] = pack2(wb.x, wb.y);
                wp[3] = pack2(wb.z, wb.w);
            }
#pragma unroll
            for (int j = 0; j < 8; j++) {
                float xv = xs[ng + 16 * j][ki];
                unsigned long long xp = pack2(xv, xv);
                fma2(acc[j][0], xp, wp[0]);
                fma2(acc[j][1], xp, wp[1]);
                fma2(acc[j][2], xp, wp[2]);
                fma2(acc[j][3], xp, wp[3]);
            }
        }
        __syncthreads();
    }

    const int h  = cg >> 2;
    const int og = (cg & 3) * 8;
    float4 as0 = *(const float4*)&at[h * (2 * OUT_DIM) + og];
    float4 as1 = *(const float4*)&at[h * (2 * OUT_DIM) + og + 4];
    float4 ad0 = *(const float4*)&at[h * (2 * OUT_DIM) + OUT_DIM + og];
    float4 ad1 = *(const float4*)&at[h * (2 * OUT_DIM) + OUT_DIM + og + 4];

#pragma unroll
    for (int j = 0; j < 8; j++) {
        int n = n0 + ng + 16 * j;
        float v0, v1, v2, v3, v4, v5, v6, v7;
        unpack2(acc[j][0], v0, v1);
        unpack2(acc[j][1], v2, v3);
        unpack2(acc[j][2], v4, v5);
        unpack2(acc[j][3], v6, v7);

        float ps = v0*as0.x + v1*as0.y + v2*as0.z + v3*as0.w
                 + v4*as1.x + v5*as1.y + v6*as1.z + v7*as1.w;
        float pd = v0*ad0.x + v1*ad0.y + v2*ad0.z + v3*ad0.w
                 + v4*ad1.x + v5*ad1.y + v6*ad1.z + v7*ad1.w;
        ps += __shfl_xor_sync(0xffffffffu, ps, 1);
        pd += __shfl_xor_sync(0xffffffffu, pd, 1);
        ps += __shfl_xor_sync(0xffffffffu, ps, 2);
        pd += __shfl_xor_sync(0xffffffffu, pd, 2);

        if (n < N_NODES) {
            *(float4*)&g_Wh[(size_t)n * TOT_OUT + cg * 8]     = make_float4(v0, v1, v2, v3);
            *(float4*)&g_Wh[(size_t)n * TOT_OUT + cg * 8 + 4] = make_float4(v4, v5, v6, v7);
            if ((cg & 3) == 0) {
                g_ssrc[n * N_HEADS + h] = ps;
                g_sdst[n * N_HEADS + h] = pd;
            }
        }
    }
}

// ---------------- kernel 2: init (zero histogram + softmax sums) -------------
__global__ void init_kernel() {
    int i = blockIdx.x * blockDim.x + threadIdx.x;
    if (i < N_NODES) g_cnt[i] = 0;
    if (i < N_NODES * N_HEADS) g_sum[i] = 0.0f;
}

// ---------------- kernel 3: degree histogram + softmax denominators ----------
// edge_index is int32 pairs (JAX x64 disabled downgrades int64 -> int32).
__global__ void hist_kernel(const int* __restrict__ ei) {
    int e = blockIdx.x * blockDim.x + threadIdx.x;
    if (e >= N_EDGES) return;
    int2 p = ((const int2*)ei)[e];
    int src = p.x, dst = p.y;
    if ((unsigned)src >= N_NODES || (unsigned)dst >= N_NODES) return;

    float4 ss = *(const float4*)&g_ssrc[src * N_HEADS];
    float4 sd = *(const float4*)&g_sdst[dst * N_HEADS];
    float4 v;
    v.x = __expf(lrelu(ss.x + sd.x));
    v.y = __expf(lrelu(ss.y + sd.y));
    v.z = __expf(lrelu(ss.z + sd.z));
    v.w = __expf(lrelu(ss.w + sd.w));

    atomicAdd(&g_cnt[dst], 1);
    redAdd4(&g_sum[dst * N_HEADS], v);
}

// ---------------- kernels 4a/4b/4c: two-level scan ---------------------------
__global__ void scan1_kernel() {
    const int tid = threadIdx.x;
    const int i   = blockIdx.x * 256 + tid;
    int v = (i < N_NODES) ? g_cnt[i] : 0;
    int incl = block_incl_scan(v, tid);
    if (i < N_NODES) g_off[i] = incl - v;
    if (tid == 255) g_blk[blockIdx.x] = incl;
}

__global__ void scan2_kernel() {
    const int tid = threadIdx.x;
    int v = (tid < SCAN_NB) ? g_blk[tid] : 0;
    int incl = block_incl_scan(v, tid);
    if (tid < SCAN_NB) g_blkoff[tid] = incl - v;
}

__global__ void scan3_kernel() {
    const int i = blockIdx.x * 256 + threadIdx.x;
    if (i < N_NODES) {
        int o = g_off[i] + g_blkoff[blockIdx.x];
        g_off[i] = o;
        g_cur[i] = o;
    }
    if (i == 0) g_off[N_NODES] = N_EDGES;
}

// ---------------- kernel 5: CSR scatter + coalesced alpha output -------------
// Sums are complete, so alpha can be written directly in edge order.
__global__ void scatter_kernel(const int* __restrict__ ei,
                               float* __restrict__ out_alpha) {
    int e = blockIdx.x * blockDim.x + threadIdx.x;
    if (e >= N_EDGES) return;
    int2 p = ((const int2*)ei)[e];
    int src = p.x, dst = p.y;
    if ((unsigned)src >= N_NODES || (unsigned)dst >= N_NODES) return;

    float4 ss = *(const float4*)&g_ssrc[src * N_HEADS];
    float4 sd = *(const float4*)&g_sdst[dst * N_HEADS];
    float4 s4 = *(const float4*)&g_sum[dst * N_HEADS];
    float4 a;
    a.x = __expf(lrelu(ss.x + sd.x)) / (s4.x + 1e-9f);
    a.y = __expf(lrelu(ss.y + sd.y)) / (s4.y + 1e-9f);
    a.z = __expf(lrelu(ss.z + sd.z)) / (s4.z + 1e-9f);
    a.w = __expf(lrelu(ss.w + sd.w)) / (s4.w + 1e-9f);
    *(float4*)&out_alpha[(size_t)e * N_HEADS] = a;   // coalesced, edge order

    int pos = atomicAdd(&g_cur[dst], 1);
    g_src[pos] = src;
}

// ---------------- kernel 6: gather (recompute alpha + weighted sum) ----------
// One warp per dst node; per-lane scalar exp recompute (lane's head only).
__global__ void gather_kernel(float* __restrict__ out_h) {
    const int warp = threadIdx.x >> 5;
    const int lane = threadIdx.x & 31;
    const int d = blockIdx.x * 8 + warp;
    if (d >= N_NODES) return;

    const int beg = g_off[d];
    const int end = g_off[d + 1];
    const int hsel = lane >> 3;

    float4 s4 = *(const float4*)&g_sum[d * N_HEADS];
    float4 sd4 = *(const float4*)&g_sdst[d * N_HEADS];
    float rcp = 1.0f / (((hsel == 0) ? s4.x : (hsel == 1) ? s4.y : (hsel == 2) ? s4.z : s4.w) + 1e-9f);
    float sd  = (hsel == 0) ? sd4.x : (hsel == 1) ? sd4.y : (hsel == 2) ? sd4.z : sd4.w;

    float4 acc = make_float4(0.f, 0.f, 0.f, 0.f);
    int i = beg;

    for (; i + 4 <= end; i += 4) {
        int s0 = g_src[i];
        int s1 = g_src[i + 1];
        int s2 = g_src[i + 2];
        int s3 = g_src[i + 3];

        float q0 = g_ssrc[s0 * N_HEADS + hsel];
        float q1 = g_ssrc[s1 * N_HEADS + hsel];
        float q2 = g_ssrc[s2 * N_HEADS + hsel];
        float q3 = g_ssrc[s3 * N_HEADS + hsel];

        float4 w0 = *(const float4*)&g_Wh[(size_t)s0 * TOT_OUT + lane * 4];
        float4 w1 = *(const float4*)&g_Wh[(size_t)s1 * TOT_OUT + lane * 4];
        float4 w2 = *(const float4*)&g_Wh[(size_t)s2 * TOT_OUT + lane * 4];
        float4 w3 = *(const float4*)&g_Wh[(size_t)s3 * TOT_OUT + lane * 4];

        float a0 = __expf(lrelu(q0 + sd)) * rcp;
        float a1 = __expf(lrelu(q1 + sd)) * rcp;
        float a2 = __expf(lrelu(q2 + sd)) * rcp;
        float a3 = __expf(lrelu(q3 + sd)) * rcp;

        acc.x += a0 * w0.x + a1 * w1.x + a2 * w2.x + a3 * w3.x;
        acc.y += a0 * w0.y + a1 * w1.y + a2 * w2.y + a3 * w3.y;
        acc.z += a0 * w0.z + a1 * w1.z + a2 * w2.z + a3 * w3.z;
        acc.w += a0 * w0.w + a1 * w1.w + a2 * w2.w + a3 * w3.w;
    }
    for (; i < end; i++) {
        int s0 = g_src[i];
        float q0 = g_ssrc[s0 * N_HEADS + hsel];
        float4 w0 = *(const float4*)&g_Wh[(size_t)s0 * TOT_OUT + lane * 4];
        float a0 = __expf(lrelu(q0 + sd)) * rcp;
        acc.x += a0 * w0.x;
        acc.y += a0 * w0.y;
        acc.z += a0 * w0.z;
        acc.w += a0 * w0.w;
    }

    *(float4*)&out_h[(size_t)d * TOT_OUT + lane * 4] = acc;
}

// ---------------- launch -----------------------------------------------------
extern "C" void kernel_launch(void* const* d_in, const int* in_sizes, int n_in,
                              void* d_out, int out_size) {
    const float* x  = (const float*)d_in[0];
    const int*   ei = (const int*)d_in[1];
    const float* wt = (const float*)d_in[2];
    const float* at = (const float*)d_in[3];

    float* out_h     = (float*)d_out;                                   // [50000*128]
    float* out_alpha = (float*)d_out + (size_t)N_NODES * TOT_OUT;       // [1.6M*4]

    // 1. projection GEMM (f32x2 packed) + fused attention-score epilogue
    gemm_kernel<<<(N_NODES + GN - 1) / GN, 256>>>(x, wt, at);

    // 2. zero histogram + softmax sums
    init_kernel<<<(N_NODES * N_HEADS + 255) / 256, 256>>>();

    // 3. degree histogram + softmax denominators (fused)
    hist_kernel<<<(N_EDGES + 255) / 256, 256>>>(ei);

    // 4. two-level parallel scan -> CSR offsets + cursors
    scan1_kernel<<<SCAN_NB, 256>>>();
    scan2_kernel<<<1, 256>>>();
    scan3_kernel<<<SCAN_NB, 256>>>();

    // 5. CSR scatter + coalesced alpha output (fused)
    scatter_kernel<<<(N_EDGES + 255) / 256, 256>>>(ei, out_alpha);

    // 6. gather: recompute alpha per edge + weighted sum per dst node
    gather_kernel<<<(N_NODES + 7) / 8, 256>>>(out_h);

    (void)in_sizes; (void)n_in; (void)out_size;
}